// round 9
// baseline (speedup 1.0000x reference)
#include <cuda_runtime.h>
#include <cuda_fp16.h>
#include <cstdint>

// ============================================================================
// TimeEmbedder: temb(t) -> standardize -> silu(x@W1+b1) -> @W2+b2
// FP16 mma.sync m16n8k16 (fp32 accum). CTA tile 128x128x64, 4 warps,
// 3-stage cp.async, 2 CTAs/SM. (R7 mainloop; trimmed setup overhead.)
// ============================================================================

#define DIM     1024
#define BATCH   32768
#define NOUT    4096   // DIM*EXP

// ---------------- scratch (device globals; no allocations allowed) ----------
__device__ __half g_temb[(size_t)BATCH * DIM];   // fp16 A of GEMM1 (64 MB)
__device__ __half g_w1t[(size_t)NOUT * DIM];     // [N,K] K-major fp16 (8 MB)
__device__ __half g_w2t[(size_t)NOUT * NOUT];    // [N,K] K-major fp16 (32 MB)
__device__ __half g_h[(size_t)BATCH * NOUT];     // fp16 A of GEMM2 (256 MB)

// ---------------- helpers ----------------------------------------------------
__device__ __forceinline__ uint32_t smem_u32(const void* p) {
    uint32_t a;
    asm("{ .reg .u64 t; cvta.to.shared.u64 t, %1; cvt.u32.u64 %0, t; }" : "=r"(a) : "l"(p));
    return a;
}
__device__ __forceinline__ uint32_t swz128(uint32_t o) { return o ^ ((o >> 3) & 0x70u); }
__device__ __forceinline__ void cp_async16(uint32_t dst, const void* src) {
    asm volatile("cp.async.cg.shared.global [%0], [%1], 16;" :: "r"(dst), "l"(src));
}
__device__ __forceinline__ void cp_commit() { asm volatile("cp.async.commit_group;"); }

__device__ __forceinline__ void ldsm_x4(uint32_t* r, uint32_t addr) {
    asm volatile("ldmatrix.sync.aligned.m8n8.x4.shared.b16 {%0,%1,%2,%3}, [%4];"
                 : "=r"(r[0]), "=r"(r[1]), "=r"(r[2]), "=r"(r[3]) : "r"(addr));
}
__device__ __forceinline__ void mma_f16(float* c, const uint32_t* a, uint32_t b0, uint32_t b1) {
    asm volatile("mma.sync.aligned.m16n8k16.row.col.f32.f16.f16.f32 "
                 "{%0,%1,%2,%3}, {%4,%5,%6,%7}, {%8,%9}, {%0,%1,%2,%3};"
                 : "+f"(c[0]), "+f"(c[1]), "+f"(c[2]), "+f"(c[3])
                 : "r"(a[0]), "r"(a[1]), "r"(a[2]), "r"(a[3]), "r"(b0), "r"(b1));
}

// ============================================================================
// Kernel 1: positional embedding + standardization -> fp16 (freq inline)
// ============================================================================
__global__ void __launch_bounds__(512) temb_kernel(const float* __restrict__ t) {
    __shared__ float s_sum[16], s_ssq[16];
    __shared__ float s_mean, s_rstd;
    int b = blockIdx.x, i = threadIdx.x;

    // geometric frequency for this channel, computed in double (matches
    // fp32(i/511) exponent then exact double pow)
    float ef = (float)i / 511.0f;
    // log2(1e-4) in double
    float freq = (float)exp2((double)ef * -13.287712379549449);

    float x = t[b] * 1000.0f;
    float p = x * freq;                           // fp32 angle, matches reference
    double pd = (double)p;
    double k  = rint(pd * 0.15915494309189535);
    double r  = fma(-k, 6.283185307179586, pd);
    float rf = (float)r;
    float c = cosf(rf), s = sinf(rf);

    float sum = c + s;
    float ssq = c * c + s * s;
    #pragma unroll
    for (int o = 16; o > 0; o >>= 1) {
        sum += __shfl_xor_sync(0xFFFFFFFFu, sum, o);
        ssq += __shfl_xor_sync(0xFFFFFFFFu, ssq, o);
    }
    if ((i & 31) == 0) { s_sum[i >> 5] = sum; s_ssq[i >> 5] = ssq; }
    __syncthreads();
    if (i == 0) {
        float S = 0.f, Q = 0.f;
        #pragma unroll
        for (int w = 0; w < 16; w++) { S += s_sum[w]; Q += s_ssq[w]; }
        float mean = S / (float)DIM;
        float var  = (Q - S * S / (float)DIM) / (float)(DIM - 1);
        s_mean = mean;
        s_rstd = rsqrtf(var);
    }
    __syncthreads();
    float mean = s_mean, rstd = s_rstd;
    float cn = (c - mean) * rstd;
    float sn = (s - mean) * rstd;
    float cn1 = __shfl_down_sync(0xFFFFFFFFu, cn, 1);
    float sn1 = __shfl_down_sync(0xFFFFFFFFu, sn, 1);
    if (!(i & 1)) {
        size_t base = (size_t)b * DIM;
        *(__half2*)&g_temb[base + i] =
            __halves2half2(__float2half_rn(cn), __float2half_rn(cn1));
        *(__half2*)&g_temb[base + 512 + i] =
            __halves2half2(__float2half_rn(sn), __float2half_rn(sn1));
    }
}

// ============================================================================
// Kernel 2: fused transpose of W1 and W2 ([K,N] fp32 -> [N,K] K-major fp16)
//   Flattened grid: first W1 tiles (128x32 = 4096 blocks), then W2 (16384).
// ============================================================================
#define W1_TILES (NOUT / 32 * (DIM / 32))    // 128 n-tiles x 32 k-tiles = 4096
__global__ void transpose_kernel(const float* __restrict__ W1src,
                                 const float* __restrict__ W2src) {
    __shared__ float tile[32][33];
    int bidx = blockIdx.x;
    const float* src;
    __half* dst;
    int K, N, n0, k0;
    if (bidx < W1_TILES) {
        src = W1src; dst = g_w1t; K = DIM; N = NOUT;
        n0 = (bidx % (NOUT / 32)) * 32;
        k0 = (bidx / (NOUT / 32)) * 32;
    } else {
        bidx -= W1_TILES;
        src = W2src; dst = g_w2t; K = NOUT; N = NOUT;
        n0 = (bidx % (NOUT / 32)) * 32;
        k0 = (bidx / (NOUT / 32)) * 32;
    }
    int tx = threadIdx.x, ty = threadIdx.y;
    #pragma unroll
    for (int i = 0; i < 32; i += 8)
        tile[ty + i][tx] = src[(size_t)(k0 + ty + i) * N + (n0 + tx)];
    __syncthreads();
    #pragma unroll
    for (int i = 0; i < 32; i += 8)
        dst[(size_t)(n0 + ty + i) * K + (k0 + tx)] = __float2half_rn(tile[tx][ty + i]);
}

// ============================================================================
// Kernel 3: FP16 mma.sync GEMM. C[m,n] = sum_k A[m,k]*Bt[n,k] (+bias, silu)
// CTA 128x128x64, 4 warps (warp 64x64), 3-stage cp.async, 2 CTAs/SM.
// ============================================================================
#define BM 128
#define BN 128
#define BK 64
#define STAGES 3
#define ASTAGE (BM * BK * 2)            // 16 KB
#define BSTAGE (BN * BK * 2)            // 16 KB
#define STAGE_BYTES (ASTAGE + BSTAGE)   // 32 KB
#define DYN_SMEM (STAGES * STAGE_BYTES) // 96 KB

template <int KTOT, bool PHASE1>
__global__ void __launch_bounds__(128, 2)
gemm_kernel(const float* __restrict__ bias, float* __restrict__ Cout) {
    const __half* A  = PHASE1 ? g_temb : g_h;
    const __half* Bt = PHASE1 ? g_w1t  : g_w2t;

    extern __shared__ char dynsmem[];
    __shared__ float s_bias[BN];

    const int tid  = threadIdx.x;
    const int wid  = tid >> 5;
    const int lane = tid & 31;
    const int n0 = blockIdx.x * BN;
    const int m0 = blockIdx.y * BM;
    const int warp_m = (wid & 1) * 64;   // 0 / 64
    const int warp_n = (wid >> 1) * 64;  // 0 / 64

    const uint32_t dyn = smem_u32(dynsmem);

    if (tid < BN) s_bias[tid] = bias[n0 + tid];

    // ---- per-thread gmem->smem load plan (16B chunks = 8 halves) ----
    const char* Ab = (const char*)A;
    const char* Bb = (const char*)Bt;
    uint32_t offA[8], dA[8], offB[8], dB[8];
    #pragma unroll
    for (int j = 0; j < 8; j++) {
        uint32_t cid = (uint32_t)j * 128u + (uint32_t)tid;
        uint32_t row = cid >> 3, kc = cid & 7;
        offA[j] = (uint32_t)(m0 + row) * (uint32_t)KTOT * 2u + kc * 16u;
        dA[j]   = swz128(row * 128u + kc * 16u);
        offB[j] = (uint32_t)(n0 + row) * (uint32_t)KTOT * 2u + kc * 16u;
        dB[j]   = (uint32_t)ASTAGE + swz128(row * 128u + kc * 16u);
    }

    // ---- ldmatrix address precompute ----
    const uint32_t lane16 = lane & 15;
    const uint32_t hiA = (lane >> 4) & 1;
    uint32_t aRow[4], aXor[4];
    #pragma unroll
    for (int mt = 0; mt < 4; mt++) {
        uint32_t r = (uint32_t)(warp_m + mt * 16) + lane16;
        aRow[mt] = r * 128u;
        aXor[mt] = r & 7u;
    }
    const uint32_t nrl = (lane & 7) | ((lane >> 1) & 8);
    const uint32_t hiB = (lane >> 3) & 1;
    uint32_t bRow[4], bXor[4];
    #pragma unroll
    for (int p = 0; p < 4; p++) {
        uint32_t r = (uint32_t)(warp_n + p * 16) + nrl;
        bRow[p] = r * 128u;
        bXor[p] = r & 7u;
    }

    float c[4][8][4];
    #pragma unroll
    for (int mt = 0; mt < 4; mt++)
        #pragma unroll
        for (int nt = 0; nt < 8; nt++)
            #pragma unroll
            for (int i = 0; i < 4; i++) c[mt][nt][i] = 0.0f;

    const int nk = KTOT / BK;

    // ---- prologue: issue stages 0..STAGES-2 ----
    #pragma unroll
    for (int j = 0; j < STAGES - 1; j++) {
        uint32_t sb = dyn + (uint32_t)j * STAGE_BYTES;
        #pragma unroll
        for (int i = 0; i < 8; i++) cp_async16(sb + dA[i], Ab + offA[i]);
        #pragma unroll
        for (int i = 0; i < 8; i++) cp_async16(sb + dB[i], Bb + offB[i]);
        #pragma unroll
        for (int i = 0; i < 8; i++) { offA[i] += 128u; offB[i] += 128u; }
        cp_commit();
    }

    // fragment double buffers
    uint32_t a[2][4][4], b[2][4][4];

    #pragma unroll 4
    for (int kt = 0; kt < nk; kt++) {
        asm volatile("cp.async.wait_group %0;" :: "n"(STAGES - 2));
        __syncthreads();

        // issue loads for stage kt+STAGES-1 into the buffer freed last iter
        if (kt + STAGES - 1 < nk) {
            uint32_t sb = dyn + (uint32_t)((kt + STAGES - 1) % STAGES) * STAGE_BYTES;
            #pragma unroll
            for (int i = 0; i < 8; i++) cp_async16(sb + dA[i], Ab + offA[i]);
            #pragma unroll
            for (int i = 0; i < 8; i++) cp_async16(sb + dB[i], Bb + offB[i]);
            #pragma unroll
            for (int i = 0; i < 8; i++) { offA[i] += 128u; offB[i] += 128u; }
        }
        cp_commit();

        uint32_t sA = dyn + (uint32_t)(kt % STAGES) * STAGE_BYTES;
        uint32_t sB = sA + ASTAGE;

        // ---- preload k-step 0 fragments ----
        #pragma unroll
        for (int mt = 0; mt < 4; mt++) {
            uint32_t col16 = hiA ^ aXor[mt];
            ldsm_x4(a[0][mt], sA + aRow[mt] + (col16 << 4));
        }
        #pragma unroll
        for (int p = 0; p < 4; p++) {
            uint32_t col16 = hiB ^ bXor[p];
            ldsm_x4(b[0][p], sB + bRow[p] + (col16 << 4));
        }

        // ---- pipelined k-steps: prefetch ks+1 while computing ks ----
        #pragma unroll
        for (int ks = 0; ks < 4; ks++) {
            const int cur = ks & 1, nxt = cur ^ 1;
            if (ks < 3) {
                #pragma unroll
                for (int mt = 0; mt < 4; mt++) {
                    uint32_t col16 = ((uint32_t)((ks + 1) * 2) + hiA) ^ aXor[mt];
                    ldsm_x4(a[nxt][mt], sA + aRow[mt] + (col16 << 4));
                }
                #pragma unroll
                for (int p = 0; p < 4; p++) {
                    uint32_t col16 = ((uint32_t)((ks + 1) * 2) + hiB) ^ bXor[p];
                    ldsm_x4(b[nxt][p], sB + bRow[p] + (col16 << 4));
                }
            }
            #pragma unroll
            for (int mt = 0; mt < 4; mt++) {
                #pragma unroll
                for (int nt = 0; nt < 8; nt++) {
                    const int p = nt >> 1;
                    if (nt & 1) mma_f16(c[mt][nt], a[cur][mt], b[cur][p][2], b[cur][p][3]);
                    else        mma_f16(c[mt][nt], a[cur][mt], b[cur][p][0], b[cur][p][1]);
                }
            }
        }
    }
    __syncthreads();   // also covers s_bias visibility

    // ---- epilogue ----
    const int ncol0 = warp_n + (lane & 3) * 2;
    #pragma unroll
    for (int mt = 0; mt < 4; mt++) {
        int r0 = m0 + warp_m + mt * 16 + (lane >> 2);
        #pragma unroll
        for (int nt = 0; nt < 8; nt++) {
            float bv0 = s_bias[ncol0 + nt * 8];
            float bv1 = s_bias[ncol0 + nt * 8 + 1];
            float v0 = c[mt][nt][0] + bv0;
            float v1 = c[mt][nt][1] + bv1;
            float v2 = c[mt][nt][2] + bv0;
            float v3 = c[mt][nt][3] + bv1;
            if (PHASE1) {
                v0 = v0 / (1.0f + __expf(-v0));
                v1 = v1 / (1.0f + __expf(-v1));
                v2 = v2 / (1.0f + __expf(-v2));
                v3 = v3 / (1.0f + __expf(-v3));
                __half* row0 = g_h + (size_t)r0 * NOUT + (n0 + ncol0);
                __half* row1 = row0 + (size_t)8 * NOUT;
                *(__half2*)(row0 + nt * 8) =
                    __halves2half2(__float2half_rn(v0), __float2half_rn(v1));
                *(__half2*)(row1 + nt * 8) =
                    __halves2half2(__float2half_rn(v2), __float2half_rn(v3));
            } else {
                float* row0 = Cout + (size_t)r0 * NOUT + (n0 + ncol0);
                float* row1 = row0 + (size_t)8 * NOUT;
                __stcs((float2*)(row0 + nt * 8), make_float2(v0, v1));
                __stcs((float2*)(row1 + nt * 8), make_float2(v2, v3));
            }
        }
    }
}

// ============================================================================
// host launcher
// ============================================================================
extern "C" void kernel_launch(void* const* d_in, const int* in_sizes, int n_in,
                              void* d_out, int out_size) {
    const float* t  = (const float*)d_in[0];
    const float* W1 = (const float*)d_in[1];
    const float* b1 = (const float*)d_in[2];
    const float* W2 = (const float*)d_in[3];
    const float* b2 = (const float*)d_in[4];
    float* out = (float*)d_out;

    cudaFuncSetAttribute(gemm_kernel<DIM, true>,
                         cudaFuncAttributeMaxDynamicSharedMemorySize, DYN_SMEM);
    cudaFuncSetAttribute(gemm_kernel<NOUT, false>,
                         cudaFuncAttributeMaxDynamicSharedMemorySize, DYN_SMEM);

    temb_kernel<<<BATCH, 512>>>(t);

    const int w2_tiles = (NOUT / 32) * (NOUT / 32);
    dim3 tb(32, 8);
    transpose_kernel<<<W1_TILES + w2_tiles, tb>>>(W1, W2);

    dim3 grid(NOUT / BN, BATCH / BM);   // (32, 256): n fastest
    gemm_kernel<DIM, true><<<grid, 128, DYN_SMEM>>>(b1, nullptr);
    gemm_kernel<NOUT, false><<<grid, 128, DYN_SMEM>>>(b2, out);
}

// round 10
// speedup vs baseline: 1.1958x; 1.1958x over previous
#include <cuda_runtime.h>
#include <cuda_fp16.h>
#include <cstdint>

// ============================================================================
// TimeEmbedder: temb(t) -> standardize -> silu(x@W1+b1) -> @W2+b2
// FP16 mma.sync m16n8k16 (fp32 accum). CTA tile 128x128x64, 4 warps,
// 3-stage cp.async, 2 CTAs/SM. (R7 mainloop; freq kernel restored.)
// ============================================================================

#define DIM     1024
#define BATCH   32768
#define NOUT    4096   // DIM*EXP

// ---------------- scratch (device globals; no allocations allowed) ----------
__device__ __half g_temb[(size_t)BATCH * DIM];   // fp16 A of GEMM1 (64 MB)
__device__ __half g_w1t[(size_t)NOUT * DIM];     // [N,K] K-major fp16 (8 MB)
__device__ __half g_w2t[(size_t)NOUT * NOUT];    // [N,K] K-major fp16 (32 MB)
__device__ __half g_h[(size_t)BATCH * NOUT];     // fp16 A of GEMM2 (256 MB)
__device__ float  g_freq[DIM / 2];

// ---------------- helpers ----------------------------------------------------
__device__ __forceinline__ uint32_t smem_u32(const void* p) {
    uint32_t a;
    asm("{ .reg .u64 t; cvta.to.shared.u64 t, %1; cvt.u32.u64 %0, t; }" : "=r"(a) : "l"(p));
    return a;
}
__device__ __forceinline__ uint32_t swz128(uint32_t o) { return o ^ ((o >> 3) & 0x70u); }
__device__ __forceinline__ void cp_async16(uint32_t dst, const void* src) {
    asm volatile("cp.async.cg.shared.global [%0], [%1], 16;" :: "r"(dst), "l"(src));
}
__device__ __forceinline__ void cp_commit() { asm volatile("cp.async.commit_group;"); }

__device__ __forceinline__ void ldsm_x4(uint32_t* r, uint32_t addr) {
    asm volatile("ldmatrix.sync.aligned.m8n8.x4.shared.b16 {%0,%1,%2,%3}, [%4];"
                 : "=r"(r[0]), "=r"(r[1]), "=r"(r[2]), "=r"(r[3]) : "r"(addr));
}
__device__ __forceinline__ void mma_f16(float* c, const uint32_t* a, uint32_t b0, uint32_t b1) {
    asm volatile("mma.sync.aligned.m16n8k16.row.col.f32.f16.f16.f32 "
                 "{%0,%1,%2,%3}, {%4,%5,%6,%7}, {%8,%9}, {%0,%1,%2,%3};"
                 : "+f"(c[0]), "+f"(c[1]), "+f"(c[2]), "+f"(c[3])
                 : "r"(a[0]), "r"(a[1]), "r"(a[2]), "r"(a[3]), "r"(b0), "r"(b1));
}

// ============================================================================
// Kernel 0: geometric frequencies (512 threads total; double pow is cheap here)
// ============================================================================
__global__ void freq_kernel() {
    int i = threadIdx.x;
    if (i < DIM / 2) {
        float ef = (float)i / 511.0f;
        g_freq[i] = (float)pow(1e-4, (double)ef);
    }
}

// ============================================================================
// Kernel 1: positional embedding + standardization -> fp16 (packed stores)
// ============================================================================
__global__ void __launch_bounds__(512) temb_kernel(const float* __restrict__ t) {
    __shared__ float s_sum[16], s_ssq[16];
    __shared__ float s_mean, s_rstd;
    int b = blockIdx.x, i = threadIdx.x;

    float x = t[b] * 1000.0f;
    float p = x * g_freq[i];                      // fp32 angle, matches reference
    double pd = (double)p;
    double k  = rint(pd * 0.15915494309189535);
    double r  = fma(-k, 6.283185307179586, pd);
    float rf = (float)r;
    float c = cosf(rf), s = sinf(rf);

    float sum = c + s;
    float ssq = c * c + s * s;
    #pragma unroll
    for (int o = 16; o > 0; o >>= 1) {
        sum += __shfl_xor_sync(0xFFFFFFFFu, sum, o);
        ssq += __shfl_xor_sync(0xFFFFFFFFu, ssq, o);
    }
    if ((i & 31) == 0) { s_sum[i >> 5] = sum; s_ssq[i >> 5] = ssq; }
    __syncthreads();
    if (i == 0) {
        float S = 0.f, Q = 0.f;
        #pragma unroll
        for (int w = 0; w < 16; w++) { S += s_sum[w]; Q += s_ssq[w]; }
        float mean = S / (float)DIM;
        float var  = (Q - S * S / (float)DIM) / (float)(DIM - 1);
        s_mean = mean;
        s_rstd = rsqrtf(var);
    }
    __syncthreads();
    float mean = s_mean, rstd = s_rstd;
    float cn = (c - mean) * rstd;
    float sn = (s - mean) * rstd;
    float cn1 = __shfl_down_sync(0xFFFFFFFFu, cn, 1);
    float sn1 = __shfl_down_sync(0xFFFFFFFFu, sn, 1);
    if (!(i & 1)) {
        size_t base = (size_t)b * DIM;
        *(__half2*)&g_temb[base + i] =
            __halves2half2(__float2half_rn(cn), __float2half_rn(cn1));
        *(__half2*)&g_temb[base + 512 + i] =
            __halves2half2(__float2half_rn(sn), __float2half_rn(sn1));
    }
}

// ============================================================================
// Kernel 2: fused transpose of W1 and W2 ([K,N] fp32 -> [N,K] K-major fp16)
// ============================================================================
#define W1_TILES (NOUT / 32 * (DIM / 32))    // 4096 tiles
__global__ void transpose_kernel(const float* __restrict__ W1src,
                                 const float* __restrict__ W2src) {
    __shared__ float tile[32][33];
    int bidx = blockIdx.x;
    const float* src;
    __half* dst;
    int K, N, n0, k0;
    if (bidx < W1_TILES) {
        src = W1src; dst = g_w1t; K = DIM; N = NOUT;
        n0 = (bidx % (NOUT / 32)) * 32;
        k0 = (bidx / (NOUT / 32)) * 32;
    } else {
        bidx -= W1_TILES;
        src = W2src; dst = g_w2t; K = NOUT; N = NOUT;
        n0 = (bidx % (NOUT / 32)) * 32;
        k0 = (bidx / (NOUT / 32)) * 32;
    }
    int tx = threadIdx.x, ty = threadIdx.y;
    #pragma unroll
    for (int i = 0; i < 32; i += 8)
        tile[ty + i][tx] = src[(size_t)(k0 + ty + i) * N + (n0 + tx)];
    __syncthreads();
    #pragma unroll
    for (int i = 0; i < 32; i += 8)
        dst[(size_t)(n0 + ty + i) * K + (k0 + tx)] = __float2half_rn(tile[tx][ty + i]);
}

// ============================================================================
// Kernel 3: FP16 mma.sync GEMM. C[m,n] = sum_k A[m,k]*Bt[n,k] (+bias, silu)
// CTA 128x128x64, 4 warps (warp 64x64), 3-stage cp.async, 2 CTAs/SM.
// ============================================================================
#define BM 128
#define BN 128
#define BK 64
#define STAGES 3
#define ASTAGE (BM * BK * 2)            // 16 KB
#define BSTAGE (BN * BK * 2)            // 16 KB
#define STAGE_BYTES (ASTAGE + BSTAGE)   // 32 KB
#define DYN_SMEM (STAGES * STAGE_BYTES) // 96 KB

template <int KTOT, bool PHASE1>
__global__ void __launch_bounds__(128, 2)
gemm_kernel(const float* __restrict__ bias, float* __restrict__ Cout) {
    const __half* A  = PHASE1 ? g_temb : g_h;
    const __half* Bt = PHASE1 ? g_w1t  : g_w2t;

    extern __shared__ char dynsmem[];
    __shared__ float s_bias[BN];

    const int tid  = threadIdx.x;
    const int wid  = tid >> 5;
    const int lane = tid & 31;
    const int n0 = blockIdx.x * BN;
    const int m0 = blockIdx.y * BM;
    const int warp_m = (wid & 1) * 64;   // 0 / 64
    const int warp_n = (wid >> 1) * 64;  // 0 / 64

    const uint32_t dyn = smem_u32(dynsmem);

    if (tid < BN) s_bias[tid] = bias[n0 + tid];

    // ---- per-thread gmem->smem load plan (16B chunks = 8 halves) ----
    const char* Ab = (const char*)A;
    const char* Bb = (const char*)Bt;
    uint32_t offA[8], dA[8], offB[8], dB[8];
    #pragma unroll
    for (int j = 0; j < 8; j++) {
        uint32_t cid = (uint32_t)j * 128u + (uint32_t)tid;
        uint32_t row = cid >> 3, kc = cid & 7;
        offA[j] = (uint32_t)(m0 + row) * (uint32_t)KTOT * 2u + kc * 16u;
        dA[j]   = swz128(row * 128u + kc * 16u);
        offB[j] = (uint32_t)(n0 + row) * (uint32_t)KTOT * 2u + kc * 16u;
        dB[j]   = (uint32_t)ASTAGE + swz128(row * 128u + kc * 16u);
    }

    // ---- ldmatrix address precompute ----
    const uint32_t lane16 = lane & 15;
    const uint32_t hiA = (lane >> 4) & 1;
    uint32_t aRow[4], aXor[4];
    #pragma unroll
    for (int mt = 0; mt < 4; mt++) {
        uint32_t r = (uint32_t)(warp_m + mt * 16) + lane16;
        aRow[mt] = r * 128u;
        aXor[mt] = r & 7u;
    }
    const uint32_t nrl = (lane & 7) | ((lane >> 1) & 8);
    const uint32_t hiB = (lane >> 3) & 1;
    uint32_t bRow[4], bXor[4];
    #pragma unroll
    for (int p = 0; p < 4; p++) {
        uint32_t r = (uint32_t)(warp_n + p * 16) + nrl;
        bRow[p] = r * 128u;
        bXor[p] = r & 7u;
    }

    float c[4][8][4];
    #pragma unroll
    for (int mt = 0; mt < 4; mt++)
        #pragma unroll
        for (int nt = 0; nt < 8; nt++)
            #pragma unroll
            for (int i = 0; i < 4; i++) c[mt][nt][i] = 0.0f;

    const int nk = KTOT / BK;

    // ---- prologue: issue stages 0..STAGES-2 ----
    #pragma unroll
    for (int j = 0; j < STAGES - 1; j++) {
        uint32_t sb = dyn + (uint32_t)j * STAGE_BYTES;
        #pragma unroll
        for (int i = 0; i < 8; i++) cp_async16(sb + dA[i], Ab + offA[i]);
        #pragma unroll
        for (int i = 0; i < 8; i++) cp_async16(sb + dB[i], Bb + offB[i]);
        #pragma unroll
        for (int i = 0; i < 8; i++) { offA[i] += 128u; offB[i] += 128u; }
        cp_commit();
    }

    // fragment double buffers
    uint32_t a[2][4][4], b[2][4][4];

    #pragma unroll 4
    for (int kt = 0; kt < nk; kt++) {
        asm volatile("cp.async.wait_group %0;" :: "n"(STAGES - 2));
        __syncthreads();

        // issue loads for stage kt+STAGES-1 into the buffer freed last iter
        if (kt + STAGES - 1 < nk) {
            uint32_t sb = dyn + (uint32_t)((kt + STAGES - 1) % STAGES) * STAGE_BYTES;
            #pragma unroll
            for (int i = 0; i < 8; i++) cp_async16(sb + dA[i], Ab + offA[i]);
            #pragma unroll
            for (int i = 0; i < 8; i++) cp_async16(sb + dB[i], Bb + offB[i]);
            #pragma unroll
            for (int i = 0; i < 8; i++) { offA[i] += 128u; offB[i] += 128u; }
        }
        cp_commit();

        uint32_t sA = dyn + (uint32_t)(kt % STAGES) * STAGE_BYTES;
        uint32_t sB = sA + ASTAGE;

        // ---- preload k-step 0 fragments ----
        #pragma unroll
        for (int mt = 0; mt < 4; mt++) {
            uint32_t col16 = hiA ^ aXor[mt];
            ldsm_x4(a[0][mt], sA + aRow[mt] + (col16 << 4));
        }
        #pragma unroll
        for (int p = 0; p < 4; p++) {
            uint32_t col16 = hiB ^ bXor[p];
            ldsm_x4(b[0][p], sB + bRow[p] + (col16 << 4));
        }

        // ---- pipelined k-steps: prefetch ks+1 while computing ks ----
        #pragma unroll
        for (int ks = 0; ks < 4; ks++) {
            const int cur = ks & 1, nxt = cur ^ 1;
            if (ks < 3) {
                #pragma unroll
                for (int mt = 0; mt < 4; mt++) {
                    uint32_t col16 = ((uint32_t)((ks + 1) * 2) + hiA) ^ aXor[mt];
                    ldsm_x4(a[nxt][mt], sA + aRow[mt] + (col16 << 4));
                }
                #pragma unroll
                for (int p = 0; p < 4; p++) {
                    uint32_t col16 = ((uint32_t)((ks + 1) * 2) + hiB) ^ bXor[p];
                    ldsm_x4(b[nxt][p], sB + bRow[p] + (col16 << 4));
                }
            }
            #pragma unroll
            for (int mt = 0; mt < 4; mt++) {
                #pragma unroll
                for (int nt = 0; nt < 8; nt++) {
                    const int p = nt >> 1;
                    if (nt & 1) mma_f16(c[mt][nt], a[cur][mt], b[cur][p][2], b[cur][p][3]);
                    else        mma_f16(c[mt][nt], a[cur][mt], b[cur][p][0], b[cur][p][1]);
                }
            }
        }
    }
    __syncthreads();   // also covers s_bias visibility

    // ---- epilogue ----
    const int ncol0 = warp_n + (lane & 3) * 2;
    #pragma unroll
    for (int mt = 0; mt < 4; mt++) {
        int r0 = m0 + warp_m + mt * 16 + (lane >> 2);
        #pragma unroll
        for (int nt = 0; nt < 8; nt++) {
            float bv0 = s_bias[ncol0 + nt * 8];
            float bv1 = s_bias[ncol0 + nt * 8 + 1];
            float v0 = c[mt][nt][0] + bv0;
            float v1 = c[mt][nt][1] + bv1;
            float v2 = c[mt][nt][2] + bv0;
            float v3 = c[mt][nt][3] + bv1;
            if (PHASE1) {
                v0 = v0 / (1.0f + __expf(-v0));
                v1 = v1 / (1.0f + __expf(-v1));
                v2 = v2 / (1.0f + __expf(-v2));
                v3 = v3 / (1.0f + __expf(-v3));
                __half* row0 = g_h + (size_t)r0 * NOUT + (n0 + ncol0);
                __half* row1 = row0 + (size_t)8 * NOUT;
                *(__half2*)(row0 + nt * 8) =
                    __halves2half2(__float2half_rn(v0), __float2half_rn(v1));
                *(__half2*)(row1 + nt * 8) =
                    __halves2half2(__float2half_rn(v2), __float2half_rn(v3));
            } else {
                float* row0 = Cout + (size_t)r0 * NOUT + (n0 + ncol0);
                float* row1 = row0 + (size_t)8 * NOUT;
                __stcs((float2*)(row0 + nt * 8), make_float2(v0, v1));
                __stcs((float2*)(row1 + nt * 8), make_float2(v2, v3));
            }
        }
    }
}

// ============================================================================
// host launcher
// ============================================================================
extern "C" void kernel_launch(void* const* d_in, const int* in_sizes, int n_in,
                              void* d_out, int out_size) {
    const float* t  = (const float*)d_in[0];
    const float* W1 = (const float*)d_in[1];
    const float* b1 = (const float*)d_in[2];
    const float* W2 = (const float*)d_in[3];
    const float* b2 = (const float*)d_in[4];
    float* out = (float*)d_out;

    cudaFuncSetAttribute(gemm_kernel<DIM, true>,
                         cudaFuncAttributeMaxDynamicSharedMemorySize, DYN_SMEM);
    cudaFuncSetAttribute(gemm_kernel<NOUT, false>,
                         cudaFuncAttributeMaxDynamicSharedMemorySize, DYN_SMEM);

    freq_kernel<<<1, 512>>>();
    temb_kernel<<<BATCH, 512>>>(t);

    const int w2_tiles = (NOUT / 32) * (NOUT / 32);
    dim3 tb(32, 8);
    transpose_kernel<<<W1_TILES + w2_tiles, tb>>>(W1, W2);

    dim3 grid(NOUT / BN, BATCH / BM);   // (32, 256): n fastest
    gemm_kernel<DIM, true><<<grid, 128, DYN_SMEM>>>(b1, nullptr);
    gemm_kernel<NOUT, false><<<grid, 128, DYN_SMEM>>>(b2, out);
}

// round 11
// speedup vs baseline: 1.2155x; 1.0164x over previous
#include <cuda_runtime.h>
#include <cuda_fp16.h>
#include <cstdint>

// ============================================================================
// TimeEmbedder: temb(t) -> standardize -> silu(x@W1+b1) -> @W2+b2
// FP16 mma.sync m16n8k16 (fp32 accum). CTA tile 128x128x64, 4 warps,
// 3-stage cp.async, 2 CTAs/SM. R10 + fast-division silu epilogue.
// ============================================================================

#define DIM     1024
#define BATCH   32768
#define NOUT    4096   // DIM*EXP

// ---------------- scratch (device globals; no allocations allowed) ----------
__device__ __half g_temb[(size_t)BATCH * DIM];   // fp16 A of GEMM1 (64 MB)
__device__ __half g_w1t[(size_t)NOUT * DIM];     // [N,K] K-major fp16 (8 MB)
__device__ __half g_w2t[(size_t)NOUT * NOUT];    // [N,K] K-major fp16 (32 MB)
__device__ __half g_h[(size_t)BATCH * NOUT];     // fp16 A of GEMM2 (256 MB)
__device__ float  g_freq[DIM / 2];

// ---------------- helpers ----------------------------------------------------
__device__ __forceinline__ uint32_t smem_u32(const void* p) {
    uint32_t a;
    asm("{ .reg .u64 t; cvta.to.shared.u64 t, %1; cvt.u32.u64 %0, t; }" : "=r"(a) : "l"(p));
    return a;
}
__device__ __forceinline__ uint32_t swz128(uint32_t o) { return o ^ ((o >> 3) & 0x70u); }
__device__ __forceinline__ void cp_async16(uint32_t dst, const void* src) {
    asm volatile("cp.async.cg.shared.global [%0], [%1], 16;" :: "r"(dst), "l"(src));
}
__device__ __forceinline__ void cp_commit() { asm volatile("cp.async.commit_group;"); }

__device__ __forceinline__ void ldsm_x4(uint32_t* r, uint32_t addr) {
    asm volatile("ldmatrix.sync.aligned.m8n8.x4.shared.b16 {%0,%1,%2,%3}, [%4];"
                 : "=r"(r[0]), "=r"(r[1]), "=r"(r[2]), "=r"(r[3]) : "r"(addr));
}
__device__ __forceinline__ void mma_f16(float* c, const uint32_t* a, uint32_t b0, uint32_t b1) {
    asm volatile("mma.sync.aligned.m16n8k16.row.col.f32.f16.f16.f32 "
                 "{%0,%1,%2,%3}, {%4,%5,%6,%7}, {%8,%9}, {%0,%1,%2,%3};"
                 : "+f"(c[0]), "+f"(c[1]), "+f"(c[2]), "+f"(c[3])
                 : "r"(a[0]), "r"(a[1]), "r"(a[2]), "r"(a[3]), "r"(b0), "r"(b1));
}
__device__ __forceinline__ float silu_fast(float v) {
    return __fdividef(v, 1.0f + __expf(-v));
}

// ============================================================================
// Kernel 0: geometric frequencies (512 threads total)
// ============================================================================
__global__ void freq_kernel() {
    int i = threadIdx.x;
    if (i < DIM / 2) {
        float ef = (float)i / 511.0f;
        g_freq[i] = (float)pow(1e-4, (double)ef);
    }
}

// ============================================================================
// Kernel 1: positional embedding + standardization -> fp16 (packed stores)
// ============================================================================
__global__ void __launch_bounds__(512) temb_kernel(const float* __restrict__ t) {
    __shared__ float s_sum[16], s_ssq[16];
    __shared__ float s_mean, s_rstd;
    int b = blockIdx.x, i = threadIdx.x;

    float x = t[b] * 1000.0f;
    float p = x * g_freq[i];                      // fp32 angle, matches reference
    double pd = (double)p;
    double k  = rint(pd * 0.15915494309189535);
    double r  = fma(-k, 6.283185307179586, pd);
    float rf = (float)r;
    float c = cosf(rf), s = sinf(rf);

    float sum = c + s;
    float ssq = c * c + s * s;
    #pragma unroll
    for (int o = 16; o > 0; o >>= 1) {
        sum += __shfl_xor_sync(0xFFFFFFFFu, sum, o);
        ssq += __shfl_xor_sync(0xFFFFFFFFu, ssq, o);
    }
    if ((i & 31) == 0) { s_sum[i >> 5] = sum; s_ssq[i >> 5] = ssq; }
    __syncthreads();
    if (i == 0) {
        float S = 0.f, Q = 0.f;
        #pragma unroll
        for (int w = 0; w < 16; w++) { S += s_sum[w]; Q += s_ssq[w]; }
        float mean = S / (float)DIM;
        float var  = (Q - S * S / (float)DIM) / (float)(DIM - 1);
        s_mean = mean;
        s_rstd = rsqrtf(var);
    }
    __syncthreads();
    float mean = s_mean, rstd = s_rstd;
    float cn = (c - mean) * rstd;
    float sn = (s - mean) * rstd;
    float cn1 = __shfl_down_sync(0xFFFFFFFFu, cn, 1);
    float sn1 = __shfl_down_sync(0xFFFFFFFFu, sn, 1);
    if (!(i & 1)) {
        size_t base = (size_t)b * DIM;
        *(__half2*)&g_temb[base + i] =
            __halves2half2(__float2half_rn(cn), __float2half_rn(cn1));
        *(__half2*)&g_temb[base + 512 + i] =
            __halves2half2(__float2half_rn(sn), __float2half_rn(sn1));
    }
}

// ============================================================================
// Kernel 2: fused transpose of W1 and W2 ([K,N] fp32 -> [N,K] K-major fp16)
// ============================================================================
#define W1_TILES (NOUT / 32 * (DIM / 32))    // 4096 tiles
__global__ void transpose_kernel(const float* __restrict__ W1src,
                                 const float* __restrict__ W2src) {
    __shared__ float tile[32][33];
    int bidx = blockIdx.x;
    const float* src;
    __half* dst;
    int K, N, n0, k0;
    if (bidx < W1_TILES) {
        src = W1src; dst = g_w1t; K = DIM; N = NOUT;
        n0 = (bidx % (NOUT / 32)) * 32;
        k0 = (bidx / (NOUT / 32)) * 32;
    } else {
        bidx -= W1_TILES;
        src = W2src; dst = g_w2t; K = NOUT; N = NOUT;
        n0 = (bidx % (NOUT / 32)) * 32;
        k0 = (bidx / (NOUT / 32)) * 32;
    }
    int tx = threadIdx.x, ty = threadIdx.y;
    #pragma unroll
    for (int i = 0; i < 32; i += 8)
        tile[ty + i][tx] = src[(size_t)(k0 + ty + i) * N + (n0 + tx)];
    __syncthreads();
    #pragma unroll
    for (int i = 0; i < 32; i += 8)
        dst[(size_t)(n0 + ty + i) * K + (k0 + tx)] = __float2half_rn(tile[tx][ty + i]);
}

// ============================================================================
// Kernel 3: FP16 mma.sync GEMM. C[m,n] = sum_k A[m,k]*Bt[n,k] (+bias, silu)
// CTA 128x128x64, 4 warps (warp 64x64), 3-stage cp.async, 2 CTAs/SM.
// ============================================================================
#define BM 128
#define BN 128
#define BK 64
#define STAGES 3
#define ASTAGE (BM * BK * 2)            // 16 KB
#define BSTAGE (BN * BK * 2)            // 16 KB
#define STAGE_BYTES (ASTAGE + BSTAGE)   // 32 KB
#define DYN_SMEM (STAGES * STAGE_BYTES) // 96 KB

template <int KTOT, bool PHASE1>
__global__ void __launch_bounds__(128, 2)
gemm_kernel(const float* __restrict__ bias, float* __restrict__ Cout) {
    const __half* A  = PHASE1 ? g_temb : g_h;
    const __half* Bt = PHASE1 ? g_w1t  : g_w2t;

    extern __shared__ char dynsmem[];
    __shared__ float s_bias[BN];

    const int tid  = threadIdx.x;
    const int wid  = tid >> 5;
    const int lane = tid & 31;
    const int n0 = blockIdx.x * BN;
    const int m0 = blockIdx.y * BM;
    const int warp_m = (wid & 1) * 64;   // 0 / 64
    const int warp_n = (wid >> 1) * 64;  // 0 / 64

    const uint32_t dyn = smem_u32(dynsmem);

    if (tid < BN) s_bias[tid] = bias[n0 + tid];

    // ---- per-thread gmem->smem load plan (16B chunks = 8 halves) ----
    const char* Ab = (const char*)A;
    const char* Bb = (const char*)Bt;
    uint32_t offA[8], dA[8], offB[8], dB[8];
    #pragma unroll
    for (int j = 0; j < 8; j++) {
        uint32_t cid = (uint32_t)j * 128u + (uint32_t)tid;
        uint32_t row = cid >> 3, kc = cid & 7;
        offA[j] = (uint32_t)(m0 + row) * (uint32_t)KTOT * 2u + kc * 16u;
        dA[j]   = swz128(row * 128u + kc * 16u);
        offB[j] = (uint32_t)(n0 + row) * (uint32_t)KTOT * 2u + kc * 16u;
        dB[j]   = (uint32_t)ASTAGE + swz128(row * 128u + kc * 16u);
    }

    // ---- ldmatrix address precompute ----
    const uint32_t lane16 = lane & 15;
    const uint32_t hiA = (lane >> 4) & 1;
    uint32_t aRow[4], aXor[4];
    #pragma unroll
    for (int mt = 0; mt < 4; mt++) {
        uint32_t r = (uint32_t)(warp_m + mt * 16) + lane16;
        aRow[mt] = r * 128u;
        aXor[mt] = r & 7u;
    }
    const uint32_t nrl = (lane & 7) | ((lane >> 1) & 8);
    const uint32_t hiB = (lane >> 3) & 1;
    uint32_t bRow[4], bXor[4];
    #pragma unroll
    for (int p = 0; p < 4; p++) {
        uint32_t r = (uint32_t)(warp_n + p * 16) + nrl;
        bRow[p] = r * 128u;
        bXor[p] = r & 7u;
    }

    float c[4][8][4];
    #pragma unroll
    for (int mt = 0; mt < 4; mt++)
        #pragma unroll
        for (int nt = 0; nt < 8; nt++)
            #pragma unroll
            for (int i = 0; i < 4; i++) c[mt][nt][i] = 0.0f;

    const int nk = KTOT / BK;

    // ---- prologue: issue stages 0..STAGES-2 ----
    #pragma unroll
    for (int j = 0; j < STAGES - 1; j++) {
        uint32_t sb = dyn + (uint32_t)j * STAGE_BYTES;
        #pragma unroll
        for (int i = 0; i < 8; i++) cp_async16(sb + dA[i], Ab + offA[i]);
        #pragma unroll
        for (int i = 0; i < 8; i++) cp_async16(sb + dB[i], Bb + offB[i]);
        #pragma unroll
        for (int i = 0; i < 8; i++) { offA[i] += 128u; offB[i] += 128u; }
        cp_commit();
    }

    // fragment double buffers
    uint32_t a[2][4][4], b[2][4][4];

    #pragma unroll 4
    for (int kt = 0; kt < nk; kt++) {
        asm volatile("cp.async.wait_group %0;" :: "n"(STAGES - 2));
        __syncthreads();

        // issue loads for stage kt+STAGES-1 into the buffer freed last iter
        if (kt + STAGES - 1 < nk) {
            uint32_t sb = dyn + (uint32_t)((kt + STAGES - 1) % STAGES) * STAGE_BYTES;
            #pragma unroll
            for (int i = 0; i < 8; i++) cp_async16(sb + dA[i], Ab + offA[i]);
            #pragma unroll
            for (int i = 0; i < 8; i++) cp_async16(sb + dB[i], Bb + offB[i]);
            #pragma unroll
            for (int i = 0; i < 8; i++) { offA[i] += 128u; offB[i] += 128u; }
        }
        cp_commit();

        uint32_t sA = dyn + (uint32_t)(kt % STAGES) * STAGE_BYTES;
        uint32_t sB = sA + ASTAGE;

        // ---- preload k-step 0 fragments ----
        #pragma unroll
        for (int mt = 0; mt < 4; mt++) {
            uint32_t col16 = hiA ^ aXor[mt];
            ldsm_x4(a[0][mt], sA + aRow[mt] + (col16 << 4));
        }
        #pragma unroll
        for (int p = 0; p < 4; p++) {
            uint32_t col16 = hiB ^ bXor[p];
            ldsm_x4(b[0][p], sB + bRow[p] + (col16 << 4));
        }

        // ---- pipelined k-steps: prefetch ks+1 while computing ks ----
        #pragma unroll
        for (int ks = 0; ks < 4; ks++) {
            const int cur = ks & 1, nxt = cur ^ 1;
            if (ks < 3) {
                #pragma unroll
                for (int mt = 0; mt < 4; mt++) {
                    uint32_t col16 = ((uint32_t)((ks + 1) * 2) + hiA) ^ aXor[mt];
                    ldsm_x4(a[nxt][mt], sA + aRow[mt] + (col16 << 4));
                }
                #pragma unroll
                for (int p = 0; p < 4; p++) {
                    uint32_t col16 = ((uint32_t)((ks + 1) * 2) + hiB) ^ bXor[p];
                    ldsm_x4(b[nxt][p], sB + bRow[p] + (col16 << 4));
                }
            }
            #pragma unroll
            for (int mt = 0; mt < 4; mt++) {
                #pragma unroll
                for (int nt = 0; nt < 8; nt++) {
                    const int p = nt >> 1;
                    if (nt & 1) mma_f16(c[mt][nt], a[cur][mt], b[cur][p][2], b[cur][p][3]);
                    else        mma_f16(c[mt][nt], a[cur][mt], b[cur][p][0], b[cur][p][1]);
                }
            }
        }
    }
    __syncthreads();   // also covers s_bias visibility

    // ---- epilogue ----
    const int ncol0 = warp_n + (lane & 3) * 2;
    #pragma unroll
    for (int mt = 0; mt < 4; mt++) {
        int r0 = m0 + warp_m + mt * 16 + (lane >> 2);
        #pragma unroll
        for (int nt = 0; nt < 8; nt++) {
            float bv0 = s_bias[ncol0 + nt * 8];
            float bv1 = s_bias[ncol0 + nt * 8 + 1];
            float v0 = c[mt][nt][0] + bv0;
            float v1 = c[mt][nt][1] + bv1;
            float v2 = c[mt][nt][2] + bv0;
            float v3 = c[mt][nt][3] + bv1;
            if (PHASE1) {
                v0 = silu_fast(v0);
                v1 = silu_fast(v1);
                v2 = silu_fast(v2);
                v3 = silu_fast(v3);
                __half* row0 = g_h + (size_t)r0 * NOUT + (n0 + ncol0);
                __half* row1 = row0 + (size_t)8 * NOUT;
                *(__half2*)(row0 + nt * 8) =
                    __halves2half2(__float2half_rn(v0), __float2half_rn(v1));
                *(__half2*)(row1 + nt * 8) =
                    __halves2half2(__float2half_rn(v2), __float2half_rn(v3));
            } else {
                float* row0 = Cout + (size_t)r0 * NOUT + (n0 + ncol0);
                float* row1 = row0 + (size_t)8 * NOUT;
                __stcs((float2*)(row0 + nt * 8), make_float2(v0, v1));
                __stcs((float2*)(row1 + nt * 8), make_float2(v2, v3));
            }
        }
    }
}

// ============================================================================
// host launcher
// ============================================================================
extern "C" void kernel_launch(void* const* d_in, const int* in_sizes, int n_in,
                              void* d_out, int out_size) {
    const float* t  = (const float*)d_in[0];
    const float* W1 = (const float*)d_in[1];
    const float* b1 = (const float*)d_in[2];
    const float* W2 = (const float*)d_in[3];
    const float* b2 = (const float*)d_in[4];
    float* out = (float*)d_out;

    cudaFuncSetAttribute(gemm_kernel<DIM, true>,
                         cudaFuncAttributeMaxDynamicSharedMemorySize, DYN_SMEM);
    cudaFuncSetAttribute(gemm_kernel<NOUT, false>,
                         cudaFuncAttributeMaxDynamicSharedMemorySize, DYN_SMEM);

    freq_kernel<<<1, 512>>>();
    temb_kernel<<<BATCH, 512>>>(t);

    const int w2_tiles = (NOUT / 32) * (NOUT / 32);
    dim3 tb(32, 8);
    transpose_kernel<<<W1_TILES + w2_tiles, tb>>>(W1, W2);

    dim3 grid(NOUT / BN, BATCH / BM);   // (32, 256): n fastest
    gemm_kernel<DIM, true><<<grid, 128, DYN_SMEM>>>(b1, nullptr);
    gemm_kernel<NOUT, false><<<grid, 128, DYN_SMEM>>>(b2, out);
}

// round 12
// speedup vs baseline: 1.2226x; 1.0059x over previous
#include <cuda_runtime.h>
#include <cuda_fp16.h>
#include <cstdint>

// ============================================================================
// TimeEmbedder: temb(t) -> standardize -> silu(x@W1+b1) -> @W2+b2
// FP16 mma.sync m16n8k16 (fp32 accum). CTA tile 128x128x64, 4 warps,
// 3-stage cp.async, 2 CTAs/SM. R11 + single-MUFU (tanh-based) silu.
// ============================================================================

#define DIM     1024
#define BATCH   32768
#define NOUT    4096   // DIM*EXP

// ---------------- scratch (device globals; no allocations allowed) ----------
__device__ __half g_temb[(size_t)BATCH * DIM];   // fp16 A of GEMM1 (64 MB)
__device__ __half g_w1t[(size_t)NOUT * DIM];     // [N,K] K-major fp16 (8 MB)
__device__ __half g_w2t[(size_t)NOUT * NOUT];    // [N,K] K-major fp16 (32 MB)
__device__ __half g_h[(size_t)BATCH * NOUT];     // fp16 A of GEMM2 (256 MB)
__device__ float  g_freq[DIM / 2];

// ---------------- helpers ----------------------------------------------------
__device__ __forceinline__ uint32_t smem_u32(const void* p) {
    uint32_t a;
    asm("{ .reg .u64 t; cvta.to.shared.u64 t, %1; cvt.u32.u64 %0, t; }" : "=r"(a) : "l"(p));
    return a;
}
__device__ __forceinline__ uint32_t swz128(uint32_t o) { return o ^ ((o >> 3) & 0x70u); }
__device__ __forceinline__ void cp_async16(uint32_t dst, const void* src) {
    asm volatile("cp.async.cg.shared.global [%0], [%1], 16;" :: "r"(dst), "l"(src));
}
__device__ __forceinline__ void cp_commit() { asm volatile("cp.async.commit_group;"); }

__device__ __forceinline__ void ldsm_x4(uint32_t* r, uint32_t addr) {
    asm volatile("ldmatrix.sync.aligned.m8n8.x4.shared.b16 {%0,%1,%2,%3}, [%4];"
                 : "=r"(r[0]), "=r"(r[1]), "=r"(r[2]), "=r"(r[3]) : "r"(addr));
}
__device__ __forceinline__ void mma_f16(float* c, const uint32_t* a, uint32_t b0, uint32_t b1) {
    asm volatile("mma.sync.aligned.m16n8k16.row.col.f32.f16.f16.f32 "
                 "{%0,%1,%2,%3}, {%4,%5,%6,%7}, {%8,%9}, {%0,%1,%2,%3};"
                 : "+f"(c[0]), "+f"(c[1]), "+f"(c[2]), "+f"(c[3])
                 : "r"(a[0]), "r"(a[1]), "r"(a[2]), "r"(a[3]), "r"(b0), "r"(b1));
}
// silu via hardware tanh: v * sigmoid(v) = v * (0.5 + 0.5*tanh(v/2)) — 1 MUFU
__device__ __forceinline__ float silu_fast(float v) {
    float t;
    asm("tanh.approx.f32 %0, %1;" : "=f"(t) : "f"(v * 0.5f));
    return v * fmaf(t, 0.5f, 0.5f);
}

// ============================================================================
// Kernel 0: geometric frequencies (512 threads total)
// ============================================================================
__global__ void freq_kernel() {
    int i = threadIdx.x;
    if (i < DIM / 2) {
        float ef = (float)i / 511.0f;
        g_freq[i] = (float)pow(1e-4, (double)ef);
    }
}

// ============================================================================
// Kernel 1: positional embedding + standardization -> fp16 (packed stores)
// ============================================================================
__global__ void __launch_bounds__(512) temb_kernel(const float* __restrict__ t) {
    __shared__ float s_sum[16], s_ssq[16];
    __shared__ float s_mean, s_rstd;
    int b = blockIdx.x, i = threadIdx.x;

    float x = t[b] * 1000.0f;
    float p = x * g_freq[i];                      // fp32 angle, matches reference
    double pd = (double)p;
    double k  = rint(pd * 0.15915494309189535);
    double r  = fma(-k, 6.283185307179586, pd);
    float rf = (float)r;
    float c = cosf(rf), s = sinf(rf);

    float sum = c + s;
    float ssq = c * c + s * s;
    #pragma unroll
    for (int o = 16; o > 0; o >>= 1) {
        sum += __shfl_xor_sync(0xFFFFFFFFu, sum, o);
        ssq += __shfl_xor_sync(0xFFFFFFFFu, ssq, o);
    }
    if ((i & 31) == 0) { s_sum[i >> 5] = sum; s_ssq[i >> 5] = ssq; }
    __syncthreads();
    if (i == 0) {
        float S = 0.f, Q = 0.f;
        #pragma unroll
        for (int w = 0; w < 16; w++) { S += s_sum[w]; Q += s_ssq[w]; }
        float mean = S / (float)DIM;
        float var  = (Q - S * S / (float)DIM) / (float)(DIM - 1);
        s_mean = mean;
        s_rstd = rsqrtf(var);
    }
    __syncthreads();
    float mean = s_mean, rstd = s_rstd;
    float cn = (c - mean) * rstd;
    float sn = (s - mean) * rstd;
    float cn1 = __shfl_down_sync(0xFFFFFFFFu, cn, 1);
    float sn1 = __shfl_down_sync(0xFFFFFFFFu, sn, 1);
    if (!(i & 1)) {
        size_t base = (size_t)b * DIM;
        *(__half2*)&g_temb[base + i] =
            __halves2half2(__float2half_rn(cn), __float2half_rn(cn1));
        *(__half2*)&g_temb[base + 512 + i] =
            __halves2half2(__float2half_rn(sn), __float2half_rn(sn1));
    }
}

// ============================================================================
// Kernel 2: fused transpose of W1 and W2 ([K,N] fp32 -> [N,K] K-major fp16)
// ============================================================================
#define W1_TILES (NOUT / 32 * (DIM / 32))    // 4096 tiles
__global__ void transpose_kernel(const float* __restrict__ W1src,
                                 const float* __restrict__ W2src) {
    __shared__ float tile[32][33];
    int bidx = blockIdx.x;
    const float* src;
    __half* dst;
    int K, N, n0, k0;
    if (bidx < W1_TILES) {
        src = W1src; dst = g_w1t; K = DIM; N = NOUT;
        n0 = (bidx % (NOUT / 32)) * 32;
        k0 = (bidx / (NOUT / 32)) * 32;
    } else {
        bidx -= W1_TILES;
        src = W2src; dst = g_w2t; K = NOUT; N = NOUT;
        n0 = (bidx % (NOUT / 32)) * 32;
        k0 = (bidx / (NOUT / 32)) * 32;
    }
    int tx = threadIdx.x, ty = threadIdx.y;
    #pragma unroll
    for (int i = 0; i < 32; i += 8)
        tile[ty + i][tx] = src[(size_t)(k0 + ty + i) * N + (n0 + tx)];
    __syncthreads();
    #pragma unroll
    for (int i = 0; i < 32; i += 8)
        dst[(size_t)(n0 + ty + i) * K + (k0 + tx)] = __float2half_rn(tile[tx][ty + i]);
}

// ============================================================================
// Kernel 3: FP16 mma.sync GEMM. C[m,n] = sum_k A[m,k]*Bt[n,k] (+bias, silu)
// CTA 128x128x64, 4 warps (warp 64x64), 3-stage cp.async, 2 CTAs/SM.
// ============================================================================
#define BM 128
#define BN 128
#define BK 64
#define STAGES 3
#define ASTAGE (BM * BK * 2)            // 16 KB
#define BSTAGE (BN * BK * 2)            // 16 KB
#define STAGE_BYTES (ASTAGE + BSTAGE)   // 32 KB
#define DYN_SMEM (STAGES * STAGE_BYTES) // 96 KB

template <int KTOT, bool PHASE1>
__global__ void __launch_bounds__(128, 2)
gemm_kernel(const float* __restrict__ bias, float* __restrict__ Cout) {
    const __half* A  = PHASE1 ? g_temb : g_h;
    const __half* Bt = PHASE1 ? g_w1t  : g_w2t;

    extern __shared__ char dynsmem[];
    __shared__ float s_bias[BN];

    const int tid  = threadIdx.x;
    const int wid  = tid >> 5;
    const int lane = tid & 31;
    const int n0 = blockIdx.x * BN;
    const int m0 = blockIdx.y * BM;
    const int warp_m = (wid & 1) * 64;   // 0 / 64
    const int warp_n = (wid >> 1) * 64;  // 0 / 64

    const uint32_t dyn = smem_u32(dynsmem);

    if (tid < BN) s_bias[tid] = bias[n0 + tid];

    // ---- per-thread gmem->smem load plan (16B chunks = 8 halves) ----
    const char* Ab = (const char*)A;
    const char* Bb = (const char*)Bt;
    uint32_t offA[8], dA[8], offB[8], dB[8];
    #pragma unroll
    for (int j = 0; j < 8; j++) {
        uint32_t cid = (uint32_t)j * 128u + (uint32_t)tid;
        uint32_t row = cid >> 3, kc = cid & 7;
        offA[j] = (uint32_t)(m0 + row) * (uint32_t)KTOT * 2u + kc * 16u;
        dA[j]   = swz128(row * 128u + kc * 16u);
        offB[j] = (uint32_t)(n0 + row) * (uint32_t)KTOT * 2u + kc * 16u;
        dB[j]   = (uint32_t)ASTAGE + swz128(row * 128u + kc * 16u);
    }

    // ---- ldmatrix address precompute ----
    const uint32_t lane16 = lane & 15;
    const uint32_t hiA = (lane >> 4) & 1;
    uint32_t aRow[4], aXor[4];
    #pragma unroll
    for (int mt = 0; mt < 4; mt++) {
        uint32_t r = (uint32_t)(warp_m + mt * 16) + lane16;
        aRow[mt] = r * 128u;
        aXor[mt] = r & 7u;
    }
    const uint32_t nrl = (lane & 7) | ((lane >> 1) & 8);
    const uint32_t hiB = (lane >> 3) & 1;
    uint32_t bRow[4], bXor[4];
    #pragma unroll
    for (int p = 0; p < 4; p++) {
        uint32_t r = (uint32_t)(warp_n + p * 16) + nrl;
        bRow[p] = r * 128u;
        bXor[p] = r & 7u;
    }

    float c[4][8][4];
    #pragma unroll
    for (int mt = 0; mt < 4; mt++)
        #pragma unroll
        for (int nt = 0; nt < 8; nt++)
            #pragma unroll
            for (int i = 0; i < 4; i++) c[mt][nt][i] = 0.0f;

    const int nk = KTOT / BK;

    // ---- prologue: issue stages 0..STAGES-2 ----
    #pragma unroll
    for (int j = 0; j < STAGES - 1; j++) {
        uint32_t sb = dyn + (uint32_t)j * STAGE_BYTES;
        #pragma unroll
        for (int i = 0; i < 8; i++) cp_async16(sb + dA[i], Ab + offA[i]);
        #pragma unroll
        for (int i = 0; i < 8; i++) cp_async16(sb + dB[i], Bb + offB[i]);
        #pragma unroll
        for (int i = 0; i < 8; i++) { offA[i] += 128u; offB[i] += 128u; }
        cp_commit();
    }

    // fragment double buffers
    uint32_t a[2][4][4], b[2][4][4];

    #pragma unroll 4
    for (int kt = 0; kt < nk; kt++) {
        asm volatile("cp.async.wait_group %0;" :: "n"(STAGES - 2));
        __syncthreads();

        // issue loads for stage kt+STAGES-1 into the buffer freed last iter
        if (kt + STAGES - 1 < nk) {
            uint32_t sb = dyn + (uint32_t)((kt + STAGES - 1) % STAGES) * STAGE_BYTES;
            #pragma unroll
            for (int i = 0; i < 8; i++) cp_async16(sb + dA[i], Ab + offA[i]);
            #pragma unroll
            for (int i = 0; i < 8; i++) cp_async16(sb + dB[i], Bb + offB[i]);
            #pragma unroll
            for (int i = 0; i < 8; i++) { offA[i] += 128u; offB[i] += 128u; }
        }
        cp_commit();

        uint32_t sA = dyn + (uint32_t)(kt % STAGES) * STAGE_BYTES;
        uint32_t sB = sA + ASTAGE;

        // ---- preload k-step 0 fragments ----
        #pragma unroll
        for (int mt = 0; mt < 4; mt++) {
            uint32_t col16 = hiA ^ aXor[mt];
            ldsm_x4(a[0][mt], sA + aRow[mt] + (col16 << 4));
        }
        #pragma unroll
        for (int p = 0; p < 4; p++) {
            uint32_t col16 = hiB ^ bXor[p];
            ldsm_x4(b[0][p], sB + bRow[p] + (col16 << 4));
        }

        // ---- pipelined k-steps: prefetch ks+1 while computing ks ----
        #pragma unroll
        for (int ks = 0; ks < 4; ks++) {
            const int cur = ks & 1, nxt = cur ^ 1;
            if (ks < 3) {
                #pragma unroll
                for (int mt = 0; mt < 4; mt++) {
                    uint32_t col16 = ((uint32_t)((ks + 1) * 2) + hiA) ^ aXor[mt];
                    ldsm_x4(a[nxt][mt], sA + aRow[mt] + (col16 << 4));
                }
                #pragma unroll
                for (int p = 0; p < 4; p++) {
                    uint32_t col16 = ((uint32_t)((ks + 1) * 2) + hiB) ^ bXor[p];
                    ldsm_x4(b[nxt][p], sB + bRow[p] + (col16 << 4));
                }
            }
            #pragma unroll
            for (int mt = 0; mt < 4; mt++) {
                #pragma unroll
                for (int nt = 0; nt < 8; nt++) {
                    const int p = nt >> 1;
                    if (nt & 1) mma_f16(c[mt][nt], a[cur][mt], b[cur][p][2], b[cur][p][3]);
                    else        mma_f16(c[mt][nt], a[cur][mt], b[cur][p][0], b[cur][p][1]);
                }
            }
        }
    }
    __syncthreads();   // also covers s_bias visibility

    // ---- epilogue ----
    const int ncol0 = warp_n + (lane & 3) * 2;
    #pragma unroll
    for (int mt = 0; mt < 4; mt++) {
        int r0 = m0 + warp_m + mt * 16 + (lane >> 2);
        #pragma unroll
        for (int nt = 0; nt < 8; nt++) {
            float bv0 = s_bias[ncol0 + nt * 8];
            float bv1 = s_bias[ncol0 + nt * 8 + 1];
            float v0 = c[mt][nt][0] + bv0;
            float v1 = c[mt][nt][1] + bv1;
            float v2 = c[mt][nt][2] + bv0;
            float v3 = c[mt][nt][3] + bv1;
            if (PHASE1) {
                v0 = silu_fast(v0);
                v1 = silu_fast(v1);
                v2 = silu_fast(v2);
                v3 = silu_fast(v3);
                __half* row0 = g_h + (size_t)r0 * NOUT + (n0 + ncol0);
                __half* row1 = row0 + (size_t)8 * NOUT;
                *(__half2*)(row0 + nt * 8) =
                    __halves2half2(__float2half_rn(v0), __float2half_rn(v1));
                *(__half2*)(row1 + nt * 8) =
                    __halves2half2(__float2half_rn(v2), __float2half_rn(v3));
            } else {
                float* row0 = Cout + (size_t)r0 * NOUT + (n0 + ncol0);
                float* row1 = row0 + (size_t)8 * NOUT;
                __stcs((float2*)(row0 + nt * 8), make_float2(v0, v1));
                __stcs((float2*)(row1 + nt * 8), make_float2(v2, v3));
            }
        }
    }
}

// ============================================================================
// host launcher
// ============================================================================
extern "C" void kernel_launch(void* const* d_in, const int* in_sizes, int n_in,
                              void* d_out, int out_size) {
    const float* t  = (const float*)d_in[0];
    const float* W1 = (const float*)d_in[1];
    const float* b1 = (const float*)d_in[2];
    const float* W2 = (const float*)d_in[3];
    const float* b2 = (const float*)d_in[4];
    float* out = (float*)d_out;

    cudaFuncSetAttribute(gemm_kernel<DIM, true>,
                         cudaFuncAttributeMaxDynamicSharedMemorySize, DYN_SMEM);
    cudaFuncSetAttribute(gemm_kernel<NOUT, false>,
                         cudaFuncAttributeMaxDynamicSharedMemorySize, DYN_SMEM);

    freq_kernel<<<1, 512>>>();
    temb_kernel<<<BATCH, 512>>>(t);

    const int w2_tiles = (NOUT / 32) * (NOUT / 32);
    dim3 tb(32, 8);
    transpose_kernel<<<W1_TILES + w2_tiles, tb>>>(W1, W2);

    dim3 grid(NOUT / BN, BATCH / BM);   // (32, 256): n fastest
    gemm_kernel<DIM, true><<<grid, 128, DYN_SMEM>>>(b1, nullptr);
    gemm_kernel<NOUT, false><<<grid, 128, DYN_SMEM>>>(b2, out);
}

// round 13
// speedup vs baseline: 1.2624x; 1.0325x over previous
#include <cuda_runtime.h>
#include <cuda_fp16.h>
#include <cstdint>

// ============================================================================
// TimeEmbedder: temb(t) -> standardize -> silu(x@W1+b1) -> @W2+b2
// FP16 mma.sync m16n8k16 (fp32 accum). CTA tile 128x128x64, 4 warps,
// 3-stage cp.async, 2 CTAs/SM. R12 + M-persistent x2 CTAs + fp32 temb.
// ============================================================================

#define DIM     1024
#define BATCH   32768
#define NOUT    4096   // DIM*EXP

// ---------------- scratch (device globals; no allocations allowed) ----------
__device__ __half g_temb[(size_t)BATCH * DIM];   // fp16 A of GEMM1 (64 MB)
__device__ __half g_w1t[(size_t)NOUT * DIM];     // [N,K] K-major fp16 (8 MB)
__device__ __half g_w2t[(size_t)NOUT * NOUT];    // [N,K] K-major fp16 (32 MB)
__device__ __half g_h[(size_t)BATCH * NOUT];     // fp16 A of GEMM2 (256 MB)
__device__ float  g_freq[DIM / 2];

// ---------------- helpers ----------------------------------------------------
__device__ __forceinline__ uint32_t smem_u32(const void* p) {
    uint32_t a;
    asm("{ .reg .u64 t; cvta.to.shared.u64 t, %1; cvt.u32.u64 %0, t; }" : "=r"(a) : "l"(p));
    return a;
}
__device__ __forceinline__ uint32_t swz128(uint32_t o) { return o ^ ((o >> 3) & 0x70u); }
__device__ __forceinline__ void cp_async16(uint32_t dst, const void* src) {
    asm volatile("cp.async.cg.shared.global [%0], [%1], 16;" :: "r"(dst), "l"(src));
}
__device__ __forceinline__ void cp_commit() { asm volatile("cp.async.commit_group;"); }

__device__ __forceinline__ void ldsm_x4(uint32_t* r, uint32_t addr) {
    asm volatile("ldmatrix.sync.aligned.m8n8.x4.shared.b16 {%0,%1,%2,%3}, [%4];"
                 : "=r"(r[0]), "=r"(r[1]), "=r"(r[2]), "=r"(r[3]) : "r"(addr));
}
__device__ __forceinline__ void mma_f16(float* c, const uint32_t* a, uint32_t b0, uint32_t b1) {
    asm volatile("mma.sync.aligned.m16n8k16.row.col.f32.f16.f16.f32 "
                 "{%0,%1,%2,%3}, {%4,%5,%6,%7}, {%8,%9}, {%0,%1,%2,%3};"
                 : "+f"(c[0]), "+f"(c[1]), "+f"(c[2]), "+f"(c[3])
                 : "r"(a[0]), "r"(a[1]), "r"(a[2]), "r"(a[3]), "r"(b0), "r"(b1));
}
// silu via hardware tanh: v * sigmoid(v) = v * (0.5 + 0.5*tanh(v/2)) — 1 MUFU
__device__ __forceinline__ float silu_fast(float v) {
    float t;
    asm("tanh.approx.f32 %0, %1;" : "=f"(t) : "f"(v * 0.5f));
    return v * fmaf(t, 0.5f, 0.5f);
}

// ============================================================================
// Kernel 0: geometric frequencies (512 threads total)
// ============================================================================
__global__ void freq_kernel() {
    int i = threadIdx.x;
    if (i < DIM / 2) {
        float ef = (float)i / 511.0f;
        g_freq[i] = (float)pow(1e-4, (double)ef);
    }
}

// ============================================================================
// Kernel 1: positional embedding + standardization -> fp16 (packed stores)
// ============================================================================
__global__ void __launch_bounds__(512) temb_kernel(const float* __restrict__ t) {
    __shared__ float s_sum[16], s_ssq[16];
    __shared__ float s_mean, s_rstd;
    int b = blockIdx.x, i = threadIdx.x;

    float x = t[b] * 1000.0f;
    float p = x * g_freq[i];                      // fp32 angle, matches reference
    float c, s;
    sincosf(p, &s, &c);

    float sum = c + s;
    float ssq = c * c + s * s;
    #pragma unroll
    for (int o = 16; o > 0; o >>= 1) {
        sum += __shfl_xor_sync(0xFFFFFFFFu, sum, o);
        ssq += __shfl_xor_sync(0xFFFFFFFFu, ssq, o);
    }
    if ((i & 31) == 0) { s_sum[i >> 5] = sum; s_ssq[i >> 5] = ssq; }
    __syncthreads();
    if (i == 0) {
        float S = 0.f, Q = 0.f;
        #pragma unroll
        for (int w = 0; w < 16; w++) { S += s_sum[w]; Q += s_ssq[w]; }
        float mean = S / (float)DIM;
        float var  = (Q - S * S / (float)DIM) / (float)(DIM - 1);
        s_mean = mean;
        s_rstd = rsqrtf(var);
    }
    __syncthreads();
    float mean = s_mean, rstd = s_rstd;
    float cn = (c - mean) * rstd;
    float sn = (s - mean) * rstd;
    float cn1 = __shfl_down_sync(0xFFFFFFFFu, cn, 1);
    float sn1 = __shfl_down_sync(0xFFFFFFFFu, sn, 1);
    if (!(i & 1)) {
        size_t base = (size_t)b * DIM;
        *(__half2*)&g_temb[base + i] =
            __halves2half2(__float2half_rn(cn), __float2half_rn(cn1));
        *(__half2*)&g_temb[base + 512 + i] =
            __halves2half2(__float2half_rn(sn), __float2half_rn(sn1));
    }
}

// ============================================================================
// Kernel 2: fused transpose of W1 and W2 ([K,N] fp32 -> [N,K] K-major fp16)
// ============================================================================
#define W1_TILES (NOUT / 32 * (DIM / 32))    // 4096 tiles
__global__ void transpose_kernel(const float* __restrict__ W1src,
                                 const float* __restrict__ W2src) {
    __shared__ float tile[32][33];
    int bidx = blockIdx.x;
    const float* src;
    __half* dst;
    int K, N, n0, k0;
    if (bidx < W1_TILES) {
        src = W1src; dst = g_w1t; K = DIM; N = NOUT;
        n0 = (bidx % (NOUT / 32)) * 32;
        k0 = (bidx / (NOUT / 32)) * 32;
    } else {
        bidx -= W1_TILES;
        src = W2src; dst = g_w2t; K = NOUT; N = NOUT;
        n0 = (bidx % (NOUT / 32)) * 32;
        k0 = (bidx / (NOUT / 32)) * 32;
    }
    int tx = threadIdx.x, ty = threadIdx.y;
    #pragma unroll
    for (int i = 0; i < 32; i += 8)
        tile[ty + i][tx] = src[(size_t)(k0 + ty + i) * N + (n0 + tx)];
    __syncthreads();
    #pragma unroll
    for (int i = 0; i < 32; i += 8)
        dst[(size_t)(n0 + ty + i) * K + (k0 + tx)] = __float2half_rn(tile[tx][ty + i]);
}

// ============================================================================
// Kernel 3: FP16 mma.sync GEMM, M-persistent x2.
// CTA covers tiles (2*blockIdx.y + {0,1})*BM; one continuous cp.async pipeline.
// ============================================================================
#define BM 128
#define BN 128
#define BK 64
#define STAGES 3
#define MTILES 2
#define ASTAGE (BM * BK * 2)            // 16 KB
#define BSTAGE (BN * BK * 2)            // 16 KB
#define STAGE_BYTES (ASTAGE + BSTAGE)   // 32 KB
#define DYN_SMEM (STAGES * STAGE_BYTES) // 96 KB

template <bool PHASE1>
__device__ __forceinline__ void gemm_epilogue(
    float (&c)[4][8][4], const float* s_bias, float* __restrict__ Cout,
    int m0, int n0, int warp_m, int warp_n, int lane)
{
    const int ncol0 = warp_n + (lane & 3) * 2;
    #pragma unroll
    for (int mt = 0; mt < 4; mt++) {
        int r0 = m0 + warp_m + mt * 16 + (lane >> 2);
        #pragma unroll
        for (int nt = 0; nt < 8; nt++) {
            float bv0 = s_bias[ncol0 + nt * 8];
            float bv1 = s_bias[ncol0 + nt * 8 + 1];
            float v0 = c[mt][nt][0] + bv0;
            float v1 = c[mt][nt][1] + bv1;
            float v2 = c[mt][nt][2] + bv0;
            float v3 = c[mt][nt][3] + bv1;
            if (PHASE1) {
                v0 = silu_fast(v0);
                v1 = silu_fast(v1);
                v2 = silu_fast(v2);
                v3 = silu_fast(v3);
                __half* row0 = g_h + (size_t)r0 * NOUT + (n0 + ncol0);
                __half* row1 = row0 + (size_t)8 * NOUT;
                *(__half2*)(row0 + nt * 8) =
                    __halves2half2(__float2half_rn(v0), __float2half_rn(v1));
                *(__half2*)(row1 + nt * 8) =
                    __halves2half2(__float2half_rn(v2), __float2half_rn(v3));
            } else {
                float* row0 = Cout + (size_t)r0 * NOUT + (n0 + ncol0);
                float* row1 = row0 + (size_t)8 * NOUT;
                __stcs((float2*)(row0 + nt * 8), make_float2(v0, v1));
                __stcs((float2*)(row1 + nt * 8), make_float2(v2, v3));
            }
        }
    }
}

template <int KTOT, bool PHASE1>
__global__ void __launch_bounds__(128, 2)
gemm_kernel(const float* __restrict__ bias, float* __restrict__ Cout) {
    const __half* A  = PHASE1 ? g_temb : g_h;
    const __half* Bt = PHASE1 ? g_w1t  : g_w2t;

    extern __shared__ char dynsmem[];
    __shared__ float s_bias[BN];

    const int tid  = threadIdx.x;
    const int wid  = tid >> 5;
    const int lane = tid & 31;
    const int n0 = blockIdx.x * BN;
    const int m0 = blockIdx.y * (MTILES * BM);   // first of MTILES m-tiles
    const int warp_m = (wid & 1) * 64;   // 0 / 64
    const int warp_n = (wid >> 1) * 64;  // 0 / 64

    const uint32_t dyn = smem_u32(dynsmem);

    if (tid < BN) s_bias[tid] = bias[n0 + tid];

    // ---- per-thread gmem->smem load plan (16B chunks = 8 halves) ----
    const char* Ab = (const char*)A;
    const char* Bb = (const char*)Bt;
    uint32_t offA[8], dA[8], offB[8], dB[8];
    #pragma unroll
    for (int j = 0; j < 8; j++) {
        uint32_t cid = (uint32_t)j * 128u + (uint32_t)tid;
        uint32_t row = cid >> 3, kc = cid & 7;
        offA[j] = (uint32_t)(m0 + row) * (uint32_t)KTOT * 2u + kc * 16u;
        dA[j]   = swz128(row * 128u + kc * 16u);
        offB[j] = (uint32_t)(n0 + row) * (uint32_t)KTOT * 2u + kc * 16u;
        dB[j]   = (uint32_t)ASTAGE + swz128(row * 128u + kc * 16u);
    }

    // ---- ldmatrix address precompute ----
    const uint32_t lane16 = lane & 15;
    const uint32_t hiA = (lane >> 4) & 1;
    uint32_t aRow[4], aXor[4];
    #pragma unroll
    for (int mt = 0; mt < 4; mt++) {
        uint32_t r = (uint32_t)(warp_m + mt * 16) + lane16;
        aRow[mt] = r * 128u;
        aXor[mt] = r & 7u;
    }
    const uint32_t nrl = (lane & 7) | ((lane >> 1) & 8);
    const uint32_t hiB = (lane >> 3) & 1;
    uint32_t bRow[4], bXor[4];
    #pragma unroll
    for (int p = 0; p < 4; p++) {
        uint32_t r = (uint32_t)(warp_n + p * 16) + nrl;
        bRow[p] = r * 128u;
        bXor[p] = r & 7u;
    }

    float c[4][8][4];
    #pragma unroll
    for (int mt = 0; mt < 4; mt++)
        #pragma unroll
        for (int nt = 0; nt < 8; nt++)
            #pragma unroll
            for (int i = 0; i < 4; i++) c[mt][nt][i] = 0.0f;

    const int nk = KTOT / BK;

    // ---- prologue: issue stages 0..STAGES-2 ----
    #pragma unroll
    for (int j = 0; j < STAGES - 1; j++) {
        uint32_t sb = dyn + (uint32_t)j * STAGE_BYTES;
        #pragma unroll
        for (int i = 0; i < 8; i++) cp_async16(sb + dA[i], Ab + offA[i]);
        #pragma unroll
        for (int i = 0; i < 8; i++) cp_async16(sb + dB[i], Bb + offB[i]);
        #pragma unroll
        for (int i = 0; i < 8; i++) { offA[i] += 128u; offB[i] += 128u; }
        cp_commit();
    }

    // fragment double buffers
    uint32_t a[2][4][4], b[2][4][4];

    for (int tt = 0; tt < MTILES; tt++) {
        #pragma unroll 4
        for (int kt = 0; kt < nk; kt++) {
            asm volatile("cp.async.wait_group %0;" :: "n"(STAGES - 2));
            __syncthreads();

            const int gi = tt * nk + kt;                 // global stage index
            const int li = gi + STAGES - 1;              // stage being loaded
            if (li == nk) {
                // boundary: A jumps to next m-tile, B rewinds to k=0
                #pragma unroll
                for (int i = 0; i < 8; i++) {
                    offA[i] += (uint32_t)(BM - 1) * (uint32_t)KTOT * 2u;
                    offB[i] -= (uint32_t)KTOT * 2u;
                }
            }
            if (li < MTILES * nk) {
                uint32_t sb = dyn + (uint32_t)(li % STAGES) * STAGE_BYTES;
                #pragma unroll
                for (int i = 0; i < 8; i++) cp_async16(sb + dA[i], Ab + offA[i]);
                #pragma unroll
                for (int i = 0; i < 8; i++) cp_async16(sb + dB[i], Bb + offB[i]);
                #pragma unroll
                for (int i = 0; i < 8; i++) { offA[i] += 128u; offB[i] += 128u; }
            }
            cp_commit();

            uint32_t sA = dyn + (uint32_t)(gi % STAGES) * STAGE_BYTES;
            uint32_t sB = sA + ASTAGE;

            // ---- preload k-step 0 fragments ----
            #pragma unroll
            for (int mt = 0; mt < 4; mt++) {
                uint32_t col16 = hiA ^ aXor[mt];
                ldsm_x4(a[0][mt], sA + aRow[mt] + (col16 << 4));
            }
            #pragma unroll
            for (int p = 0; p < 4; p++) {
                uint32_t col16 = hiB ^ bXor[p];
                ldsm_x4(b[0][p], sB + bRow[p] + (col16 << 4));
            }

            // ---- pipelined k-steps: prefetch ks+1 while computing ks ----
            #pragma unroll
            for (int ks = 0; ks < 4; ks++) {
                const int cur = ks & 1, nxt = cur ^ 1;
                if (ks < 3) {
                    #pragma unroll
                    for (int mt = 0; mt < 4; mt++) {
                        uint32_t col16 = ((uint32_t)((ks + 1) * 2) + hiA) ^ aXor[mt];
                        ldsm_x4(a[nxt][mt], sA + aRow[mt] + (col16 << 4));
                    }
                    #pragma unroll
                    for (int p = 0; p < 4; p++) {
                        uint32_t col16 = ((uint32_t)((ks + 1) * 2) + hiB) ^ bXor[p];
                        ldsm_x4(b[nxt][p], sB + bRow[p] + (col16 << 4));
                    }
                }
                #pragma unroll
                for (int mt = 0; mt < 4; mt++) {
                    #pragma unroll
                    for (int nt = 0; nt < 8; nt++) {
                        const int p = nt >> 1;
                        if (nt & 1) mma_f16(c[mt][nt], a[cur][mt], b[cur][p][2], b[cur][p][3]);
                        else        mma_f16(c[mt][nt], a[cur][mt], b[cur][p][0], b[cur][p][1]);
                    }
                }
            }
        }

        // ---- epilogue for this m-tile (pipeline for next tile stays in flight) ----
        gemm_epilogue<PHASE1>(c, s_bias, Cout, m0 + tt * BM, n0, warp_m, warp_n, lane);
        if (tt + 1 < MTILES) {
            #pragma unroll
            for (int mt = 0; mt < 4; mt++)
                #pragma unroll
                for (int nt = 0; nt < 8; nt++)
                    #pragma unroll
                    for (int i = 0; i < 4; i++) c[mt][nt][i] = 0.0f;
        }
    }
}

// ============================================================================
// host launcher
// ============================================================================
extern "C" void kernel_launch(void* const* d_in, const int* in_sizes, int n_in,
                              void* d_out, int out_size) {
    const float* t  = (const float*)d_in[0];
    const float* W1 = (const float*)d_in[1];
    const float* b1 = (const float*)d_in[2];
    const float* W2 = (const float*)d_in[3];
    const float* b2 = (const float*)d_in[4];
    float* out = (float*)d_out;

    cudaFuncSetAttribute(gemm_kernel<DIM, true>,
                         cudaFuncAttributeMaxDynamicSharedMemorySize, DYN_SMEM);
    cudaFuncSetAttribute(gemm_kernel<NOUT, false>,
                         cudaFuncAttributeMaxDynamicSharedMemorySize, DYN_SMEM);

    freq_kernel<<<1, 512>>>();
    temb_kernel<<<BATCH, 512>>>(t);

    const int w2_tiles = (NOUT / 32) * (NOUT / 32);
    dim3 tb(32, 8);
    transpose_kernel<<<W1_TILES + w2_tiles, tb>>>(W1, W2);

    dim3 grid(NOUT / BN, BATCH / (MTILES * BM));   // (32, 128)
    gemm_kernel<DIM, true><<<grid, 128, DYN_SMEM>>>(b1, nullptr);
    gemm_kernel<NOUT, false><<<grid, 128, DYN_SMEM>>>(b2, out);
}

// round 14
// speedup vs baseline: 1.2696x; 1.0057x over previous
#include <cuda_runtime.h>
#include <cuda_fp16.h>
#include <cstdint>

// ============================================================================
// TimeEmbedder: temb(t) -> standardize -> silu(x@W1+b1) -> @W2+b2
// FP16 mma.sync m16n8k16 (fp32 accum). CTA tile 128x128x64, 4 warps,
// 3-stage cp.async, 2 CTAs/SM. M-persistent: x4 for GEMM1 (nk=16), x2 for
// GEMM2 (nk=64) — amortizes pipeline fill + setup per phase.
// ============================================================================

#define DIM     1024
#define BATCH   32768
#define NOUT    4096   // DIM*EXP

// ---------------- scratch (device globals; no allocations allowed) ----------
__device__ __half g_temb[(size_t)BATCH * DIM];   // fp16 A of GEMM1 (64 MB)
__device__ __half g_w1t[(size_t)NOUT * DIM];     // [N,K] K-major fp16 (8 MB)
__device__ __half g_w2t[(size_t)NOUT * NOUT];    // [N,K] K-major fp16 (32 MB)
__device__ __half g_h[(size_t)BATCH * NOUT];     // fp16 A of GEMM2 (256 MB)
__device__ float  g_freq[DIM / 2];

// ---------------- helpers ----------------------------------------------------
__device__ __forceinline__ uint32_t smem_u32(const void* p) {
    uint32_t a;
    asm("{ .reg .u64 t; cvta.to.shared.u64 t, %1; cvt.u32.u64 %0, t; }" : "=r"(a) : "l"(p));
    return a;
}
__device__ __forceinline__ uint32_t swz128(uint32_t o) { return o ^ ((o >> 3) & 0x70u); }
__device__ __forceinline__ void cp_async16(uint32_t dst, const void* src) {
    asm volatile("cp.async.cg.shared.global [%0], [%1], 16;" :: "r"(dst), "l"(src));
}
__device__ __forceinline__ void cp_commit() { asm volatile("cp.async.commit_group;"); }

__device__ __forceinline__ void ldsm_x4(uint32_t* r, uint32_t addr) {
    asm volatile("ldmatrix.sync.aligned.m8n8.x4.shared.b16 {%0,%1,%2,%3}, [%4];"
                 : "=r"(r[0]), "=r"(r[1]), "=r"(r[2]), "=r"(r[3]) : "r"(addr));
}
__device__ __forceinline__ void mma_f16(float* c, const uint32_t* a, uint32_t b0, uint32_t b1) {
    asm volatile("mma.sync.aligned.m16n8k16.row.col.f32.f16.f16.f32 "
                 "{%0,%1,%2,%3}, {%4,%5,%6,%7}, {%8,%9}, {%0,%1,%2,%3};"
                 : "+f"(c[0]), "+f"(c[1]), "+f"(c[2]), "+f"(c[3])
                 : "r"(a[0]), "r"(a[1]), "r"(a[2]), "r"(a[3]), "r"(b0), "r"(b1));
}
// silu via hardware tanh: v * sigmoid(v) = v * (0.5 + 0.5*tanh(v/2)) — 1 MUFU
__device__ __forceinline__ float silu_fast(float v) {
    float t;
    asm("tanh.approx.f32 %0, %1;" : "=f"(t) : "f"(v * 0.5f));
    return v * fmaf(t, 0.5f, 0.5f);
}

// ============================================================================
// Kernel 0: geometric frequencies (512 threads total)
// ============================================================================
__global__ void freq_kernel() {
    int i = threadIdx.x;
    if (i < DIM / 2) {
        float ef = (float)i / 511.0f;
        g_freq[i] = (float)pow(1e-4, (double)ef);
    }
}

// ============================================================================
// Kernel 1: positional embedding + standardization -> fp16 (packed stores)
// ============================================================================
__global__ void __launch_bounds__(512) temb_kernel(const float* __restrict__ t) {
    __shared__ float s_sum[16], s_ssq[16];
    __shared__ float s_mean, s_rstd;
    int b = blockIdx.x, i = threadIdx.x;

    float x = t[b] * 1000.0f;
    float p = x * g_freq[i];                      // fp32 angle, matches reference
    float c, s;
    sincosf(p, &s, &c);

    float sum = c + s;
    float ssq = c * c + s * s;
    #pragma unroll
    for (int o = 16; o > 0; o >>= 1) {
        sum += __shfl_xor_sync(0xFFFFFFFFu, sum, o);
        ssq += __shfl_xor_sync(0xFFFFFFFFu, ssq, o);
    }
    if ((i & 31) == 0) { s_sum[i >> 5] = sum; s_ssq[i >> 5] = ssq; }
    __syncthreads();
    if (i == 0) {
        float S = 0.f, Q = 0.f;
        #pragma unroll
        for (int w = 0; w < 16; w++) { S += s_sum[w]; Q += s_ssq[w]; }
        float mean = S / (float)DIM;
        float var  = (Q - S * S / (float)DIM) / (float)(DIM - 1);
        s_mean = mean;
        s_rstd = rsqrtf(var);
    }
    __syncthreads();
    float mean = s_mean, rstd = s_rstd;
    float cn = (c - mean) * rstd;
    float sn = (s - mean) * rstd;
    float cn1 = __shfl_down_sync(0xFFFFFFFFu, cn, 1);
    float sn1 = __shfl_down_sync(0xFFFFFFFFu, sn, 1);
    if (!(i & 1)) {
        size_t base = (size_t)b * DIM;
        *(__half2*)&g_temb[base + i] =
            __halves2half2(__float2half_rn(cn), __float2half_rn(cn1));
        *(__half2*)&g_temb[base + 512 + i] =
            __halves2half2(__float2half_rn(sn), __float2half_rn(sn1));
    }
}

// ============================================================================
// Kernel 2: fused transpose of W1 and W2 ([K,N] fp32 -> [N,K] K-major fp16)
// ============================================================================
#define W1_TILES (NOUT / 32 * (DIM / 32))    // 4096 tiles
__global__ void transpose_kernel(const float* __restrict__ W1src,
                                 const float* __restrict__ W2src) {
    __shared__ float tile[32][33];
    int bidx = blockIdx.x;
    const float* src;
    __half* dst;
    int K, N, n0, k0;
    if (bidx < W1_TILES) {
        src = W1src; dst = g_w1t; K = DIM; N = NOUT;
        n0 = (bidx % (NOUT / 32)) * 32;
        k0 = (bidx / (NOUT / 32)) * 32;
    } else {
        bidx -= W1_TILES;
        src = W2src; dst = g_w2t; K = NOUT; N = NOUT;
        n0 = (bidx % (NOUT / 32)) * 32;
        k0 = (bidx / (NOUT / 32)) * 32;
    }
    int tx = threadIdx.x, ty = threadIdx.y;
    #pragma unroll
    for (int i = 0; i < 32; i += 8)
        tile[ty + i][tx] = src[(size_t)(k0 + ty + i) * N + (n0 + tx)];
    __syncthreads();
    #pragma unroll
    for (int i = 0; i < 32; i += 8)
        dst[(size_t)(n0 + ty + i) * K + (k0 + tx)] = __float2half_rn(tile[tx][ty + i]);
}

// ============================================================================
// Kernel 3: FP16 mma.sync GEMM, M-persistent x MTILES.
// ============================================================================
#define BM 128
#define BN 128
#define BK 64
#define STAGES 3
#define ASTAGE (BM * BK * 2)            // 16 KB
#define BSTAGE (BN * BK * 2)            // 16 KB
#define STAGE_BYTES (ASTAGE + BSTAGE)   // 32 KB
#define DYN_SMEM (STAGES * STAGE_BYTES) // 96 KB

template <bool PHASE1>
__device__ __forceinline__ void gemm_epilogue(
    float (&c)[4][8][4], const float* s_bias, float* __restrict__ Cout,
    int m0, int n0, int warp_m, int warp_n, int lane)
{
    const int ncol0 = warp_n + (lane & 3) * 2;
    #pragma unroll
    for (int mt = 0; mt < 4; mt++) {
        int r0 = m0 + warp_m + mt * 16 + (lane >> 2);
        #pragma unroll
        for (int nt = 0; nt < 8; nt++) {
            float bv0 = s_bias[ncol0 + nt * 8];
            float bv1 = s_bias[ncol0 + nt * 8 + 1];
            float v0 = c[mt][nt][0] + bv0;
            float v1 = c[mt][nt][1] + bv1;
            float v2 = c[mt][nt][2] + bv0;
            float v3 = c[mt][nt][3] + bv1;
            if (PHASE1) {
                v0 = silu_fast(v0);
                v1 = silu_fast(v1);
                v2 = silu_fast(v2);
                v3 = silu_fast(v3);
                __half* row0 = g_h + (size_t)r0 * NOUT + (n0 + ncol0);
                __half* row1 = row0 + (size_t)8 * NOUT;
                *(__half2*)(row0 + nt * 8) =
                    __halves2half2(__float2half_rn(v0), __float2half_rn(v1));
                *(__half2*)(row1 + nt * 8) =
                    __halves2half2(__float2half_rn(v2), __float2half_rn(v3));
            } else {
                float* row0 = Cout + (size_t)r0 * NOUT + (n0 + ncol0);
                float* row1 = row0 + (size_t)8 * NOUT;
                __stcs((float2*)(row0 + nt * 8), make_float2(v0, v1));
                __stcs((float2*)(row1 + nt * 8), make_float2(v2, v3));
            }
        }
    }
}

template <int KTOT, bool PHASE1, int MTILES>
__global__ void __launch_bounds__(128, 2)
gemm_kernel(const float* __restrict__ bias, float* __restrict__ Cout) {
    const __half* A  = PHASE1 ? g_temb : g_h;
    const __half* Bt = PHASE1 ? g_w1t  : g_w2t;

    extern __shared__ char dynsmem[];
    __shared__ float s_bias[BN];

    const int tid  = threadIdx.x;
    const int wid  = tid >> 5;
    const int lane = tid & 31;
    const int n0 = blockIdx.x * BN;
    const int m0 = blockIdx.y * (MTILES * BM);   // first of MTILES m-tiles
    const int warp_m = (wid & 1) * 64;   // 0 / 64
    const int warp_n = (wid >> 1) * 64;  // 0 / 64

    const uint32_t dyn = smem_u32(dynsmem);

    if (tid < BN) s_bias[tid] = bias[n0 + tid];

    // ---- per-thread gmem->smem load plan (16B chunks = 8 halves) ----
    const char* Ab = (const char*)A;
    const char* Bb = (const char*)Bt;
    uint32_t offA[8], dA[8], offB[8], dB[8];
    #pragma unroll
    for (int j = 0; j < 8; j++) {
        uint32_t cid = (uint32_t)j * 128u + (uint32_t)tid;
        uint32_t row = cid >> 3, kc = cid & 7;
        offA[j] = (uint32_t)(m0 + row) * (uint32_t)KTOT * 2u + kc * 16u;
        dA[j]   = swz128(row * 128u + kc * 16u);
        offB[j] = (uint32_t)(n0 + row) * (uint32_t)KTOT * 2u + kc * 16u;
        dB[j]   = (uint32_t)ASTAGE + swz128(row * 128u + kc * 16u);
    }

    // ---- ldmatrix address precompute ----
    const uint32_t lane16 = lane & 15;
    const uint32_t hiA = (lane >> 4) & 1;
    uint32_t aRow[4], aXor[4];
    #pragma unroll
    for (int mt = 0; mt < 4; mt++) {
        uint32_t r = (uint32_t)(warp_m + mt * 16) + lane16;
        aRow[mt] = r * 128u;
        aXor[mt] = r & 7u;
    }
    const uint32_t nrl = (lane & 7) | ((lane >> 1) & 8);
    const uint32_t hiB = (lane >> 3) & 1;
    uint32_t bRow[4], bXor[4];
    #pragma unroll
    for (int p = 0; p < 4; p++) {
        uint32_t r = (uint32_t)(warp_n + p * 16) + nrl;
        bRow[p] = r * 128u;
        bXor[p] = r & 7u;
    }

    float c[4][8][4];
    #pragma unroll
    for (int mt = 0; mt < 4; mt++)
        #pragma unroll
        for (int nt = 0; nt < 8; nt++)
            #pragma unroll
            for (int i = 0; i < 4; i++) c[mt][nt][i] = 0.0f;

    const int nk = KTOT / BK;

    // ---- prologue: issue stages 0..STAGES-2 ----
    #pragma unroll
    for (int j = 0; j < STAGES - 1; j++) {
        uint32_t sb = dyn + (uint32_t)j * STAGE_BYTES;
        #pragma unroll
        for (int i = 0; i < 8; i++) cp_async16(sb + dA[i], Ab + offA[i]);
        #pragma unroll
        for (int i = 0; i < 8; i++) cp_async16(sb + dB[i], Bb + offB[i]);
        #pragma unroll
        for (int i = 0; i < 8; i++) { offA[i] += 128u; offB[i] += 128u; }
        cp_commit();
    }

    // fragment double buffers
    uint32_t a[2][4][4], b[2][4][4];

    for (int tt = 0; tt < MTILES; tt++) {
        #pragma unroll 4
        for (int kt = 0; kt < nk; kt++) {
            asm volatile("cp.async.wait_group %0;" :: "n"(STAGES - 2));
            __syncthreads();

            const int gi = tt * nk + kt;                 // global stage index
            const int li = gi + STAGES - 1;              // stage being loaded
            if (li < MTILES * nk) {
                if ((li % nk) == 0 && li > 0) {
                    // boundary: A jumps to next m-tile, B rewinds to k=0
                    #pragma unroll
                    for (int i = 0; i < 8; i++) {
                        offA[i] += (uint32_t)(BM - 1) * (uint32_t)KTOT * 2u;
                        offB[i] -= (uint32_t)KTOT * 2u;
                    }
                }
                uint32_t sb = dyn + (uint32_t)(li % STAGES) * STAGE_BYTES;
                #pragma unroll
                for (int i = 0; i < 8; i++) cp_async16(sb + dA[i], Ab + offA[i]);
                #pragma unroll
                for (int i = 0; i < 8; i++) cp_async16(sb + dB[i], Bb + offB[i]);
                #pragma unroll
                for (int i = 0; i < 8; i++) { offA[i] += 128u; offB[i] += 128u; }
            }
            cp_commit();

            uint32_t sA = dyn + (uint32_t)(gi % STAGES) * STAGE_BYTES;
            uint32_t sB = sA + ASTAGE;

            // ---- preload k-step 0 fragments ----
            #pragma unroll
            for (int mt = 0; mt < 4; mt++) {
                uint32_t col16 = hiA ^ aXor[mt];
                ldsm_x4(a[0][mt], sA + aRow[mt] + (col16 << 4));
            }
            #pragma unroll
            for (int p = 0; p < 4; p++) {
                uint32_t col16 = hiB ^ bXor[p];
                ldsm_x4(b[0][p], sB + bRow[p] + (col16 << 4));
            }

            // ---- pipelined k-steps: prefetch ks+1 while computing ks ----
            #pragma unroll
            for (int ks = 0; ks < 4; ks++) {
                const int cur = ks & 1, nxt = cur ^ 1;
                if (ks < 3) {
                    #pragma unroll
                    for (int mt = 0; mt < 4; mt++) {
                        uint32_t col16 = ((uint32_t)((ks + 1) * 2) + hiA) ^ aXor[mt];
                        ldsm_x4(a[nxt][mt], sA + aRow[mt] + (col16 << 4));
                    }
                    #pragma unroll
                    for (int p = 0; p < 4; p++) {
                        uint32_t col16 = ((uint32_t)((ks + 1) * 2) + hiB) ^ bXor[p];
                        ldsm_x4(b[nxt][p], sB + bRow[p] + (col16 << 4));
                    }
                }
                #pragma unroll
                for (int mt = 0; mt < 4; mt++) {
                    #pragma unroll
                    for (int nt = 0; nt < 8; nt++) {
                        const int p = nt >> 1;
                        if (nt & 1) mma_f16(c[mt][nt], a[cur][mt], b[cur][p][2], b[cur][p][3]);
                        else        mma_f16(c[mt][nt], a[cur][mt], b[cur][p][0], b[cur][p][1]);
                    }
                }
            }
        }

        // ---- epilogue for this m-tile (pipeline for next tile stays in flight) ----
        gemm_epilogue<PHASE1>(c, s_bias, Cout, m0 + tt * BM, n0, warp_m, warp_n, lane);
        if (tt + 1 < MTILES) {
            #pragma unroll
            for (int mt = 0; mt < 4; mt++)
                #pragma unroll
                for (int nt = 0; nt < 8; nt++)
                    #pragma unroll
                    for (int i = 0; i < 4; i++) c[mt][nt][i] = 0.0f;
        }
    }
}

// ============================================================================
// host launcher
// ============================================================================
extern "C" void kernel_launch(void* const* d_in, const int* in_sizes, int n_in,
                              void* d_out, int out_size) {
    const float* t  = (const float*)d_in[0];
    const float* W1 = (const float*)d_in[1];
    const float* b1 = (const float*)d_in[2];
    const float* W2 = (const float*)d_in[3];
    const float* b2 = (const float*)d_in[4];
    float* out = (float*)d_out;

    cudaFuncSetAttribute(gemm_kernel<DIM, true, 4>,
                         cudaFuncAttributeMaxDynamicSharedMemorySize, DYN_SMEM);
    cudaFuncSetAttribute(gemm_kernel<NOUT, false, 2>,
                         cudaFuncAttributeMaxDynamicSharedMemorySize, DYN_SMEM);

    freq_kernel<<<1, 512>>>();
    temb_kernel<<<BATCH, 512>>>(t);

    const int w2_tiles = (NOUT / 32) * (NOUT / 32);
    dim3 tb(32, 8);
    transpose_kernel<<<W1_TILES + w2_tiles, tb>>>(W1, W2);

    dim3 grid1(NOUT / BN, BATCH / (4 * BM));   // (32, 64)
    gemm_kernel<DIM, true, 4><<<grid1, 128, DYN_SMEM>>>(b1, nullptr);
    dim3 grid2(NOUT / BN, BATCH / (2 * BM));   // (32, 128)
    gemm_kernel<NOUT, false, 2><<<grid2, 128, DYN_SMEM>>>(b2, out);
}

// round 15
// speedup vs baseline: 1.2748x; 1.0041x over previous
#include <cuda_runtime.h>
#include <cuda_fp16.h>
#include <cstdint>

// ============================================================================
// TimeEmbedder: temb(t) -> standardize -> silu(x@W1+b1) -> @W2+b2
// FP16 mma.sync m16n8k16 (fp32 accum). CTA tile 128x128x64, 4 warps,
// 3-stage cp.async, 2 CTAs/SM, M-persistent x2 (both phases).
// ============================================================================

#define DIM     1024
#define BATCH   32768
#define NOUT    4096   // DIM*EXP

// ---------------- scratch (device globals; no allocations allowed) ----------
__device__ __half g_temb[(size_t)BATCH * DIM];   // fp16 A of GEMM1 (64 MB)
__device__ __half g_w1t[(size_t)NOUT * DIM];     // [N,K] K-major fp16 (8 MB)
__device__ __half g_w2t[(size_t)NOUT * NOUT];    // [N,K] K-major fp16 (32 MB)
__device__ __half g_h[(size_t)BATCH * NOUT];     // fp16 A of GEMM2 (256 MB)
__device__ float  g_freq[DIM / 2];

// ---------------- helpers ----------------------------------------------------
__device__ __forceinline__ uint32_t smem_u32(const void* p) {
    uint32_t a;
    asm("{ .reg .u64 t; cvta.to.shared.u64 t, %1; cvt.u32.u64 %0, t; }" : "=r"(a) : "l"(p));
    return a;
}
__device__ __forceinline__ uint32_t swz128(uint32_t o) { return o ^ ((o >> 3) & 0x70u); }
__device__ __forceinline__ void cp_async16(uint32_t dst, const void* src) {
    asm volatile("cp.async.cg.shared.global [%0], [%1], 16;" :: "r"(dst), "l"(src));
}
__device__ __forceinline__ void cp_commit() { asm volatile("cp.async.commit_group;"); }

__device__ __forceinline__ void ldsm_x4(uint32_t* r, uint32_t addr) {
    asm volatile("ldmatrix.sync.aligned.m8n8.x4.shared.b16 {%0,%1,%2,%3}, [%4];"
                 : "=r"(r[0]), "=r"(r[1]), "=r"(r[2]), "=r"(r[3]) : "r"(addr));
}
__device__ __forceinline__ void mma_f16(float* c, const uint32_t* a, uint32_t b0, uint32_t b1) {
    asm volatile("mma.sync.aligned.m16n8k16.row.col.f32.f16.f16.f32 "
                 "{%0,%1,%2,%3}, {%4,%5,%6,%7}, {%8,%9}, {%0,%1,%2,%3};"
                 : "+f"(c[0]), "+f"(c[1]), "+f"(c[2]), "+f"(c[3])
                 : "r"(a[0]), "r"(a[1]), "r"(a[2]), "r"(a[3]), "r"(b0), "r"(b1));
}
// silu via hardware tanh: v * sigmoid(v) = v * (0.5 + 0.5*tanh(v/2)) — 1 MUFU
__device__ __forceinline__ float silu_fast(float v) {
    float t;
    asm("tanh.approx.f32 %0, %1;" : "=f"(t) : "f"(v * 0.5f));
    return v * fmaf(t, 0.5f, 0.5f);
}

// ============================================================================
// Kernel 0: geometric frequencies (512 threads total)
// ============================================================================
__global__ void freq_kernel() {
    int i = threadIdx.x;
    if (i < DIM / 2) {
        float ef = (float)i / 511.0f;
        g_freq[i] = (float)pow(1e-4, (double)ef);
    }
}

// ============================================================================
// Kernel 1: positional embedding + standardization -> fp16 (packed stores)
// ============================================================================
__global__ void __launch_bounds__(512) temb_kernel(const float* __restrict__ t) {
    __shared__ float s_sum[16], s_ssq[16];
    __shared__ float s_mean, s_rstd;
    int b = blockIdx.x, i = threadIdx.x;

    float x = t[b] * 1000.0f;
    float p = x * g_freq[i];                      // fp32 angle, matches reference
    float c, s;
    sincosf(p, &s, &c);

    float sum = c + s;
    float ssq = c * c + s * s;
    #pragma unroll
    for (int o = 16; o > 0; o >>= 1) {
        sum += __shfl_xor_sync(0xFFFFFFFFu, sum, o);
        ssq += __shfl_xor_sync(0xFFFFFFFFu, ssq, o);
    }
    if ((i & 31) == 0) { s_sum[i >> 5] = sum; s_ssq[i >> 5] = ssq; }
    __syncthreads();
    if (i == 0) {
        float S = 0.f, Q = 0.f;
        #pragma unroll
        for (int w = 0; w < 16; w++) { S += s_sum[w]; Q += s_ssq[w]; }
        float mean = S / (float)DIM;
        float var  = (Q - S * S / (float)DIM) / (float)(DIM - 1);
        s_mean = mean;
        s_rstd = rsqrtf(var);
    }
    __syncthreads();
    float mean = s_mean, rstd = s_rstd;
    float cn = (c - mean) * rstd;
    float sn = (s - mean) * rstd;
    float cn1 = __shfl_down_sync(0xFFFFFFFFu, cn, 1);
    float sn1 = __shfl_down_sync(0xFFFFFFFFu, sn, 1);
    if (!(i & 1)) {
        size_t base = (size_t)b * DIM;
        *(__half2*)&g_temb[base + i] =
            __halves2half2(__float2half_rn(cn), __float2half_rn(cn1));
        *(__half2*)&g_temb[base + 512 + i] =
            __halves2half2(__float2half_rn(sn), __float2half_rn(sn1));
    }
}

// ============================================================================
// Kernel 2: fused transpose of W1 and W2 ([K,N] fp32 -> [N,K] K-major fp16)
// ============================================================================
#define W1_TILES (NOUT / 32 * (DIM / 32))    // 4096 tiles
__global__ void transpose_kernel(const float* __restrict__ W1src,
                                 const float* __restrict__ W2src) {
    __shared__ float tile[32][33];
    int bidx = blockIdx.x;
    const float* src;
    __half* dst;
    int K, N, n0, k0;
    if (bidx < W1_TILES) {
        src = W1src; dst = g_w1t; K = DIM; N = NOUT;
        n0 = (bidx % (NOUT / 32)) * 32;
        k0 = (bidx / (NOUT / 32)) * 32;
    } else {
        bidx -= W1_TILES;
        src = W2src; dst = g_w2t; K = NOUT; N = NOUT;
        n0 = (bidx % (NOUT / 32)) * 32;
        k0 = (bidx / (NOUT / 32)) * 32;
    }
    int tx = threadIdx.x, ty = threadIdx.y;
    #pragma unroll
    for (int i = 0; i < 32; i += 8)
        tile[ty + i][tx] = src[(size_t)(k0 + ty + i) * N + (n0 + tx)];
    __syncthreads();
    #pragma unroll
    for (int i = 0; i < 32; i += 8)
        dst[(size_t)(n0 + ty + i) * K + (k0 + tx)] = __float2half_rn(tile[tx][ty + i]);
}

// ============================================================================
// Kernel 3: FP16 mma.sync GEMM, M-persistent x MTILES.
// ============================================================================
#define BM 128
#define BN 128
#define BK 64
#define STAGES 3
#define ASTAGE (BM * BK * 2)            // 16 KB
#define BSTAGE (BN * BK * 2)            // 16 KB
#define STAGE_BYTES (ASTAGE + BSTAGE)   // 32 KB
#define DYN_SMEM (STAGES * STAGE_BYTES) // 96 KB

template <bool PHASE1>
__device__ __forceinline__ void gemm_epilogue(
    float (&c)[4][8][4], const float* s_bias, float* __restrict__ Cout,
    int m0, int n0, int warp_m, int warp_n, int lane)
{
    const int ncol0 = warp_n + (lane & 3) * 2;
    #pragma unroll
    for (int mt = 0; mt < 4; mt++) {
        int r0 = m0 + warp_m + mt * 16 + (lane >> 2);
        #pragma unroll
        for (int nt = 0; nt < 8; nt++) {
            float bv0 = s_bias[ncol0 + nt * 8];
            float bv1 = s_bias[ncol0 + nt * 8 + 1];
            float v0 = c[mt][nt][0] + bv0;
            float v1 = c[mt][nt][1] + bv1;
            float v2 = c[mt][nt][2] + bv0;
            float v3 = c[mt][nt][3] + bv1;
            if (PHASE1) {
                v0 = silu_fast(v0);
                v1 = silu_fast(v1);
                v2 = silu_fast(v2);
                v3 = silu_fast(v3);
                __half* row0 = g_h + (size_t)r0 * NOUT + (n0 + ncol0);
                __half* row1 = row0 + (size_t)8 * NOUT;
                *(__half2*)(row0 + nt * 8) =
                    __halves2half2(__float2half_rn(v0), __float2half_rn(v1));
                *(__half2*)(row1 + nt * 8) =
                    __halves2half2(__float2half_rn(v2), __float2half_rn(v3));
            } else {
                float* row0 = Cout + (size_t)r0 * NOUT + (n0 + ncol0);
                float* row1 = row0 + (size_t)8 * NOUT;
                __stcs((float2*)(row0 + nt * 8), make_float2(v0, v1));
                __stcs((float2*)(row1 + nt * 8), make_float2(v2, v3));
            }
        }
    }
}

template <int KTOT, bool PHASE1, int MTILES>
__global__ void __launch_bounds__(128, 2)
gemm_kernel(const float* __restrict__ bias, float* __restrict__ Cout) {
    const __half* A  = PHASE1 ? g_temb : g_h;
    const __half* Bt = PHASE1 ? g_w1t  : g_w2t;

    extern __shared__ char dynsmem[];
    __shared__ float s_bias[BN];

    const int tid  = threadIdx.x;
    const int wid  = tid >> 5;
    const int lane = tid & 31;
    const int n0 = blockIdx.x * BN;
    const int m0 = blockIdx.y * (MTILES * BM);   // first of MTILES m-tiles
    const int warp_m = (wid & 1) * 64;   // 0 / 64
    const int warp_n = (wid >> 1) * 64;  // 0 / 64

    const uint32_t dyn = smem_u32(dynsmem);

    if (tid < BN) s_bias[tid] = bias[n0 + tid];

    // ---- per-thread gmem->smem load plan (16B chunks = 8 halves) ----
    const char* Ab = (const char*)A;
    const char* Bb = (const char*)Bt;
    uint32_t offA[8], dA[8], offB[8], dB[8];
    #pragma unroll
    for (int j = 0; j < 8; j++) {
        uint32_t cid = (uint32_t)j * 128u + (uint32_t)tid;
        uint32_t row = cid >> 3, kc = cid & 7;
        offA[j] = (uint32_t)(m0 + row) * (uint32_t)KTOT * 2u + kc * 16u;
        dA[j]   = swz128(row * 128u + kc * 16u);
        offB[j] = (uint32_t)(n0 + row) * (uint32_t)KTOT * 2u + kc * 16u;
        dB[j]   = (uint32_t)ASTAGE + swz128(row * 128u + kc * 16u);
    }

    // ---- ldmatrix address precompute ----
    const uint32_t lane16 = lane & 15;
    const uint32_t hiA = (lane >> 4) & 1;
    uint32_t aRow[4], aXor[4];
    #pragma unroll
    for (int mt = 0; mt < 4; mt++) {
        uint32_t r = (uint32_t)(warp_m + mt * 16) + lane16;
        aRow[mt] = r * 128u;
        aXor[mt] = r & 7u;
    }
    const uint32_t nrl = (lane & 7) | ((lane >> 1) & 8);
    const uint32_t hiB = (lane >> 3) & 1;
    uint32_t bRow[4], bXor[4];
    #pragma unroll
    for (int p = 0; p < 4; p++) {
        uint32_t r = (uint32_t)(warp_n + p * 16) + nrl;
        bRow[p] = r * 128u;
        bXor[p] = r & 7u;
    }

    float c[4][8][4];
    #pragma unroll
    for (int mt = 0; mt < 4; mt++)
        #pragma unroll
        for (int nt = 0; nt < 8; nt++)
            #pragma unroll
            for (int i = 0; i < 4; i++) c[mt][nt][i] = 0.0f;

    const int nk = KTOT / BK;

    // ---- prologue: issue stages 0..STAGES-2 ----
    #pragma unroll
    for (int j = 0; j < STAGES - 1; j++) {
        uint32_t sb = dyn + (uint32_t)j * STAGE_BYTES;
        #pragma unroll
        for (int i = 0; i < 8; i++) cp_async16(sb + dA[i], Ab + offA[i]);
        #pragma unroll
        for (int i = 0; i < 8; i++) cp_async16(sb + dB[i], Bb + offB[i]);
        #pragma unroll
        for (int i = 0; i < 8; i++) { offA[i] += 128u; offB[i] += 128u; }
        cp_commit();
    }

    // fragment double buffers
    uint32_t a[2][4][4], b[2][4][4];

    for (int tt = 0; tt < MTILES; tt++) {
        #pragma unroll 4
        for (int kt = 0; kt < nk; kt++) {
            asm volatile("cp.async.wait_group %0;" :: "n"(STAGES - 2));
            __syncthreads();

            const int gi = tt * nk + kt;                 // global stage index
            const int li = gi + STAGES - 1;              // stage being loaded
            if (li < MTILES * nk) {
                if ((li % nk) == 0 && li > 0) {
                    // boundary: A jumps to next m-tile, B rewinds to k=0
                    #pragma unroll
                    for (int i = 0; i < 8; i++) {
                        offA[i] += (uint32_t)(BM - 1) * (uint32_t)KTOT * 2u;
                        offB[i] -= (uint32_t)KTOT * 2u;
                    }
                }
                uint32_t sb = dyn + (uint32_t)(li % STAGES) * STAGE_BYTES;
                #pragma unroll
                for (int i = 0; i < 8; i++) cp_async16(sb + dA[i], Ab + offA[i]);
                #pragma unroll
                for (int i = 0; i < 8; i++) cp_async16(sb + dB[i], Bb + offB[i]);
                #pragma unroll
                for (int i = 0; i < 8; i++) { offA[i] += 128u; offB[i] += 128u; }
            }
            cp_commit();

            uint32_t sA = dyn + (uint32_t)(gi % STAGES) * STAGE_BYTES;
            uint32_t sB = sA + ASTAGE;

            // ---- preload k-step 0 fragments ----
            #pragma unroll
            for (int mt = 0; mt < 4; mt++) {
                uint32_t col16 = hiA ^ aXor[mt];
                ldsm_x4(a[0][mt], sA + aRow[mt] + (col16 << 4));
            }
            #pragma unroll
            for (int p = 0; p < 4; p++) {
                uint32_t col16 = hiB ^ bXor[p];
                ldsm_x4(b[0][p], sB + bRow[p] + (col16 << 4));
            }

            // ---- pipelined k-steps: prefetch ks+1 while computing ks ----
            #pragma unroll
            for (int ks = 0; ks < 4; ks++) {
                const int cur = ks & 1, nxt = cur ^ 1;
                if (ks < 3) {
                    #pragma unroll
                    for (int mt = 0; mt < 4; mt++) {
                        uint32_t col16 = ((uint32_t)((ks + 1) * 2) + hiA) ^ aXor[mt];
                        ldsm_x4(a[nxt][mt], sA + aRow[mt] + (col16 << 4));
                    }
                    #pragma unroll
                    for (int p = 0; p < 4; p++) {
                        uint32_t col16 = ((uint32_t)((ks + 1) * 2) + hiB) ^ bXor[p];
                        ldsm_x4(b[nxt][p], sB + bRow[p] + (col16 << 4));
                    }
                }
                #pragma unroll
                for (int mt = 0; mt < 4; mt++) {
                    #pragma unroll
                    for (int nt = 0; nt < 8; nt++) {
                        const int p = nt >> 1;
                        if (nt & 1) mma_f16(c[mt][nt], a[cur][mt], b[cur][p][2], b[cur][p][3]);
                        else        mma_f16(c[mt][nt], a[cur][mt], b[cur][p][0], b[cur][p][1]);
                    }
                }
            }
        }

        // ---- epilogue for this m-tile (pipeline for next tile stays in flight) ----
        gemm_epilogue<PHASE1>(c, s_bias, Cout, m0 + tt * BM, n0, warp_m, warp_n, lane);
        if (tt + 1 < MTILES) {
            #pragma unroll
            for (int mt = 0; mt < 4; mt++)
                #pragma unroll
                for (int nt = 0; nt < 8; nt++)
                    #pragma unroll
                    for (int i = 0; i < 4; i++) c[mt][nt][i] = 0.0f;
        }
    }
}

// ============================================================================
// host launcher
// ============================================================================
extern "C" void kernel_launch(void* const* d_in, const int* in_sizes, int n_in,
                              void* d_out, int out_size) {
    const float* t  = (const float*)d_in[0];
    const float* W1 = (const float*)d_in[1];
    const float* b1 = (const float*)d_in[2];
    const float* W2 = (const float*)d_in[3];
    const float* b2 = (const float*)d_in[4];
    float* out = (float*)d_out;

    cudaFuncSetAttribute(gemm_kernel<DIM, true, 2>,
                         cudaFuncAttributeMaxDynamicSharedMemorySize, DYN_SMEM);
    cudaFuncSetAttribute(gemm_kernel<NOUT, false, 2>,
                         cudaFuncAttributeMaxDynamicSharedMemorySize, DYN_SMEM);

    freq_kernel<<<1, 512>>>();
    temb_kernel<<<BATCH, 512>>>(t);

    const int w2_tiles = (NOUT / 32) * (NOUT / 32);
    dim3 tb(32, 8);
    transpose_kernel<<<W1_TILES + w2_tiles, tb>>>(W1, W2);

    dim3 grid(NOUT / BN, BATCH / (2 * BM));   // (32, 128)
    gemm_kernel<DIM, true, 2><<<grid, 128, DYN_SMEM>>>(b1, nullptr);
    gemm_kernel<NOUT, false, 2><<<grid, 128, DYN_SMEM>>>(b2, out);
}

// round 16
// speedup vs baseline: 1.2773x; 1.0020x over previous
#include <cuda_runtime.h>
#include <cuda_fp16.h>
#include <cstdint>

// ============================================================================
// TimeEmbedder: temb(t) -> standardize -> silu(x@W1+b1) -> @W2+b2
// FP16 mma.sync m16n8k16 (fp32 accum). CTA tile 128x128x64, 4 warps,
// 3-stage cp.async, 2 CTAs/SM, M-persistent x2. Launch DAG: W2-transpose
// overlapped with temb/W1-transpose/GEMM1 on a second stream.
// ============================================================================

#define DIM     1024
#define BATCH   32768
#define NOUT    4096   // DIM*EXP

// ---------------- scratch (device globals; no allocations allowed) ----------
__device__ __half g_temb[(size_t)BATCH * DIM];   // fp16 A of GEMM1 (64 MB)
__device__ __half g_w1t[(size_t)NOUT * DIM];     // [N,K] K-major fp16 (8 MB)
__device__ __half g_w2t[(size_t)NOUT * NOUT];    // [N,K] K-major fp16 (32 MB)
__device__ __half g_h[(size_t)BATCH * NOUT];     // fp16 A of GEMM2 (256 MB)
__device__ float  g_freq[DIM / 2];

// ---------------- helpers ----------------------------------------------------
__device__ __forceinline__ uint32_t smem_u32(const void* p) {
    uint32_t a;
    asm("{ .reg .u64 t; cvta.to.shared.u64 t, %1; cvt.u32.u64 %0, t; }" : "=r"(a) : "l"(p));
    return a;
}
__device__ __forceinline__ uint32_t swz128(uint32_t o) { return o ^ ((o >> 3) & 0x70u); }
__device__ __forceinline__ void cp_async16(uint32_t dst, const void* src) {
    asm volatile("cp.async.cg.shared.global [%0], [%1], 16;" :: "r"(dst), "l"(src));
}
__device__ __forceinline__ void cp_commit() { asm volatile("cp.async.commit_group;"); }

__device__ __forceinline__ void ldsm_x4(uint32_t* r, uint32_t addr) {
    asm volatile("ldmatrix.sync.aligned.m8n8.x4.shared.b16 {%0,%1,%2,%3}, [%4];"
                 : "=r"(r[0]), "=r"(r[1]), "=r"(r[2]), "=r"(r[3]) : "r"(addr));
}
__device__ __forceinline__ void mma_f16(float* c, const uint32_t* a, uint32_t b0, uint32_t b1) {
    asm volatile("mma.sync.aligned.m16n8k16.row.col.f32.f16.f16.f32 "
                 "{%0,%1,%2,%3}, {%4,%5,%6,%7}, {%8,%9}, {%0,%1,%2,%3};"
                 : "+f"(c[0]), "+f"(c[1]), "+f"(c[2]), "+f"(c[3])
                 : "r"(a[0]), "r"(a[1]), "r"(a[2]), "r"(a[3]), "r"(b0), "r"(b1));
}
// silu via hardware tanh: v * sigmoid(v) = v * (0.5 + 0.5*tanh(v/2)) — 1 MUFU
__device__ __forceinline__ float silu_fast(float v) {
    float t;
    asm("tanh.approx.f32 %0, %1;" : "=f"(t) : "f"(v * 0.5f));
    return v * fmaf(t, 0.5f, 0.5f);
}

// ============================================================================
// Kernel 0: geometric frequencies (512 threads total)
// ============================================================================
__global__ void freq_kernel() {
    int i = threadIdx.x;
    if (i < DIM / 2) {
        float ef = (float)i / 511.0f;
        g_freq[i] = (float)pow(1e-4, (double)ef);
    }
}

// ============================================================================
// Kernel 1: positional embedding + standardization -> fp16 (packed stores)
// ============================================================================
__global__ void __launch_bounds__(512) temb_kernel(const float* __restrict__ t) {
    __shared__ float s_sum[16], s_ssq[16];
    __shared__ float s_mean, s_rstd;
    int b = blockIdx.x, i = threadIdx.x;

    float x = t[b] * 1000.0f;
    float p = x * g_freq[i];                      // fp32 angle, matches reference
    float c, s;
    sincosf(p, &s, &c);

    float sum = c + s;
    float ssq = c * c + s * s;
    #pragma unroll
    for (int o = 16; o > 0; o >>= 1) {
        sum += __shfl_xor_sync(0xFFFFFFFFu, sum, o);
        ssq += __shfl_xor_sync(0xFFFFFFFFu, ssq, o);
    }
    if ((i & 31) == 0) { s_sum[i >> 5] = sum; s_ssq[i >> 5] = ssq; }
    __syncthreads();
    if (i == 0) {
        float S = 0.f, Q = 0.f;
        #pragma unroll
        for (int w = 0; w < 16; w++) { S += s_sum[w]; Q += s_ssq[w]; }
        float mean = S / (float)DIM;
        float var  = (Q - S * S / (float)DIM) / (float)(DIM - 1);
        s_mean = mean;
        s_rstd = rsqrtf(var);
    }
    __syncthreads();
    float mean = s_mean, rstd = s_rstd;
    float cn = (c - mean) * rstd;
    float sn = (s - mean) * rstd;
    float cn1 = __shfl_down_sync(0xFFFFFFFFu, cn, 1);
    float sn1 = __shfl_down_sync(0xFFFFFFFFu, sn, 1);
    if (!(i & 1)) {
        size_t base = (size_t)b * DIM;
        *(__half2*)&g_temb[base + i] =
            __halves2half2(__float2half_rn(cn), __float2half_rn(cn1));
        *(__half2*)&g_temb[base + 512 + i] =
            __halves2half2(__float2half_rn(sn), __float2half_rn(sn1));
    }
}

// ============================================================================
// Kernel 2: W [K,N] row-major fp32 -> WT [N,K] K-major fp16 (which: 0=W1,1=W2)
// ============================================================================
__global__ void transpose_kernel(const float* __restrict__ src, int K, int N, int which) {
    __half* dst = which ? g_w2t : g_w1t;
    __shared__ float tile[32][33];
    int n0 = blockIdx.x * 32, k0 = blockIdx.y * 32;
    int tx = threadIdx.x, ty = threadIdx.y;
    #pragma unroll
    for (int i = 0; i < 32; i += 8)
        tile[ty + i][tx] = src[(size_t)(k0 + ty + i) * N + (n0 + tx)];
    __syncthreads();
    #pragma unroll
    for (int i = 0; i < 32; i += 8)
        dst[(size_t)(n0 + ty + i) * K + (k0 + tx)] = __float2half_rn(tile[tx][ty + i]);
}

// ============================================================================
// Kernel 3: FP16 mma.sync GEMM, M-persistent x MTILES.
// ============================================================================
#define BM 128
#define BN 128
#define BK 64
#define STAGES 3
#define ASTAGE (BM * BK * 2)            // 16 KB
#define BSTAGE (BN * BK * 2)            // 16 KB
#define STAGE_BYTES (ASTAGE + BSTAGE)   // 32 KB
#define DYN_SMEM (STAGES * STAGE_BYTES) // 96 KB

template <bool PHASE1>
__device__ __forceinline__ void gemm_epilogue(
    float (&c)[4][8][4], const float* s_bias, float* __restrict__ Cout,
    int m0, int n0, int warp_m, int warp_n, int lane)
{
    const int ncol0 = warp_n + (lane & 3) * 2;
    #pragma unroll
    for (int mt = 0; mt < 4; mt++) {
        int r0 = m0 + warp_m + mt * 16 + (lane >> 2);
        #pragma unroll
        for (int nt = 0; nt < 8; nt++) {
            float bv0 = s_bias[ncol0 + nt * 8];
            float bv1 = s_bias[ncol0 + nt * 8 + 1];
            float v0 = c[mt][nt][0] + bv0;
            float v1 = c[mt][nt][1] + bv1;
            float v2 = c[mt][nt][2] + bv0;
            float v3 = c[mt][nt][3] + bv1;
            if (PHASE1) {
                v0 = silu_fast(v0);
                v1 = silu_fast(v1);
                v2 = silu_fast(v2);
                v3 = silu_fast(v3);
                __half* row0 = g_h + (size_t)r0 * NOUT + (n0 + ncol0);
                __half* row1 = row0 + (size_t)8 * NOUT;
                *(__half2*)(row0 + nt * 8) =
                    __halves2half2(__float2half_rn(v0), __float2half_rn(v1));
                *(__half2*)(row1 + nt * 8) =
                    __halves2half2(__float2half_rn(v2), __float2half_rn(v3));
            } else {
                float* row0 = Cout + (size_t)r0 * NOUT + (n0 + ncol0);
                float* row1 = row0 + (size_t)8 * NOUT;
                __stcs((float2*)(row0 + nt * 8), make_float2(v0, v1));
                __stcs((float2*)(row1 + nt * 8), make_float2(v2, v3));
            }
        }
    }
}

template <int KTOT, bool PHASE1, int MTILES>
__global__ void __launch_bounds__(128, 2)
gemm_kernel(const float* __restrict__ bias, float* __restrict__ Cout) {
    const __half* A  = PHASE1 ? g_temb : g_h;
    const __half* Bt = PHASE1 ? g_w1t  : g_w2t;

    extern __shared__ char dynsmem[];
    __shared__ float s_bias[BN];

    const int tid  = threadIdx.x;
    const int wid  = tid >> 5;
    const int lane = tid & 31;
    const int n0 = blockIdx.x * BN;
    const int m0 = blockIdx.y * (MTILES * BM);   // first of MTILES m-tiles
    const int warp_m = (wid & 1) * 64;   // 0 / 64
    const int warp_n = (wid >> 1) * 64;  // 0 / 64

    const uint32_t dyn = smem_u32(dynsmem);

    if (tid < BN) s_bias[tid] = bias[n0 + tid];

    // ---- per-thread gmem->smem load plan (16B chunks = 8 halves) ----
    const char* Ab = (const char*)A;
    const char* Bb = (const char*)Bt;
    uint32_t offA[8], dA[8], offB[8], dB[8];
    #pragma unroll
    for (int j = 0; j < 8; j++) {
        uint32_t cid = (uint32_t)j * 128u + (uint32_t)tid;
        uint32_t row = cid >> 3, kc = cid & 7;
        offA[j] = (uint32_t)(m0 + row) * (uint32_t)KTOT * 2u + kc * 16u;
        dA[j]   = swz128(row * 128u + kc * 16u);
        offB[j] = (uint32_t)(n0 + row) * (uint32_t)KTOT * 2u + kc * 16u;
        dB[j]   = (uint32_t)ASTAGE + swz128(row * 128u + kc * 16u);
    }

    // ---- ldmatrix address precompute ----
    const uint32_t lane16 = lane & 15;
    const uint32_t hiA = (lane >> 4) & 1;
    uint32_t aRow[4], aXor[4];
    #pragma unroll
    for (int mt = 0; mt < 4; mt++) {
        uint32_t r = (uint32_t)(warp_m + mt * 16) + lane16;
        aRow[mt] = r * 128u;
        aXor[mt] = r & 7u;
    }
    const uint32_t nrl = (lane & 7) | ((lane >> 1) & 8);
    const uint32_t hiB = (lane >> 3) & 1;
    uint32_t bRow[4], bXor[4];
    #pragma unroll
    for (int p = 0; p < 4; p++) {
        uint32_t r = (uint32_t)(warp_n + p * 16) + nrl;
        bRow[p] = r * 128u;
        bXor[p] = r & 7u;
    }

    float c[4][8][4];
    #pragma unroll
    for (int mt = 0; mt < 4; mt++)
        #pragma unroll
        for (int nt = 0; nt < 8; nt++)
            #pragma unroll
            for (int i = 0; i < 4; i++) c[mt][nt][i] = 0.0f;

    const int nk = KTOT / BK;

    // ---- prologue: issue stages 0..STAGES-2 ----
    #pragma unroll
    for (int j = 0; j < STAGES - 1; j++) {
        uint32_t sb = dyn + (uint32_t)j * STAGE_BYTES;
        #pragma unroll
        for (int i = 0; i < 8; i++) cp_async16(sb + dA[i], Ab + offA[i]);
        #pragma unroll
        for (int i = 0; i < 8; i++) cp_async16(sb + dB[i], Bb + offB[i]);
        #pragma unroll
        for (int i = 0; i < 8; i++) { offA[i] += 128u; offB[i] += 128u; }
        cp_commit();
    }

    // fragment double buffers
    uint32_t a[2][4][4], b[2][4][4];

    for (int tt = 0; tt < MTILES; tt++) {
        #pragma unroll 4
        for (int kt = 0; kt < nk; kt++) {
            asm volatile("cp.async.wait_group %0;" :: "n"(STAGES - 2));
            __syncthreads();

            const int gi = tt * nk + kt;                 // global stage index
            const int li = gi + STAGES - 1;              // stage being loaded
            if (li < MTILES * nk) {
                if ((li % nk) == 0 && li > 0) {
                    // boundary: A jumps to next m-tile, B rewinds to k=0
                    #pragma unroll
                    for (int i = 0; i < 8; i++) {
                        offA[i] += (uint32_t)(BM - 1) * (uint32_t)KTOT * 2u;
                        offB[i] -= (uint32_t)KTOT * 2u;
                    }
                }
                uint32_t sb = dyn + (uint32_t)(li % STAGES) * STAGE_BYTES;
                #pragma unroll
                for (int i = 0; i < 8; i++) cp_async16(sb + dA[i], Ab + offA[i]);
                #pragma unroll
                for (int i = 0; i < 8; i++) cp_async16(sb + dB[i], Bb + offB[i]);
                #pragma unroll
                for (int i = 0; i < 8; i++) { offA[i] += 128u; offB[i] += 128u; }
            }
            cp_commit();

            uint32_t sA = dyn + (uint32_t)(gi % STAGES) * STAGE_BYTES;
            uint32_t sB = sA + ASTAGE;

            // ---- preload k-step 0 fragments ----
            #pragma unroll
            for (int mt = 0; mt < 4; mt++) {
                uint32_t col16 = hiA ^ aXor[mt];
                ldsm_x4(a[0][mt], sA + aRow[mt] + (col16 << 4));
            }
            #pragma unroll
            for (int p = 0; p < 4; p++) {
                uint32_t col16 = hiB ^ bXor[p];
                ldsm_x4(b[0][p], sB + bRow[p] + (col16 << 4));
            }

            // ---- pipelined k-steps: prefetch ks+1 while computing ks ----
            #pragma unroll
            for (int ks = 0; ks < 4; ks++) {
                const int cur = ks & 1, nxt = cur ^ 1;
                if (ks < 3) {
                    #pragma unroll
                    for (int mt = 0; mt < 4; mt++) {
                        uint32_t col16 = ((uint32_t)((ks + 1) * 2) + hiA) ^ aXor[mt];
                        ldsm_x4(a[nxt][mt], sA + aRow[mt] + (col16 << 4));
                    }
                    #pragma unroll
                    for (int p = 0; p < 4; p++) {
                        uint32_t col16 = ((uint32_t)((ks + 1) * 2) + hiB) ^ bXor[p];
                        ldsm_x4(b[nxt][p], sB + bRow[p] + (col16 << 4));
                    }
                }
                #pragma unroll
                for (int mt = 0; mt < 4; mt++) {
                    #pragma unroll
                    for (int nt = 0; nt < 8; nt++) {
                        const int p = nt >> 1;
                        if (nt & 1) mma_f16(c[mt][nt], a[cur][mt], b[cur][p][2], b[cur][p][3]);
                        else        mma_f16(c[mt][nt], a[cur][mt], b[cur][p][0], b[cur][p][1]);
                    }
                }
            }
        }

        // ---- epilogue for this m-tile (pipeline for next tile stays in flight) ----
        gemm_epilogue<PHASE1>(c, s_bias, Cout, m0 + tt * BM, n0, warp_m, warp_n, lane);
        if (tt + 1 < MTILES) {
            #pragma unroll
            for (int mt = 0; mt < 4; mt++)
                #pragma unroll
                for (int nt = 0; nt < 8; nt++)
                    #pragma unroll
                    for (int i = 0; i < 4; i++) c[mt][nt][i] = 0.0f;
        }
    }
}

// ============================================================================
// host launcher — W2 transpose overlapped with temb/W1T/GEMM1 on stream 2.
// Stream/events created lazily on the first (uncaptured) correctness call;
// the captured graph then contains the fork/join DAG.
// ============================================================================
extern "C" void kernel_launch(void* const* d_in, const int* in_sizes, int n_in,
                              void* d_out, int out_size) {
    const float* t  = (const float*)d_in[0];
    const float* W1 = (const float*)d_in[1];
    const float* b1 = (const float*)d_in[2];
    const float* W2 = (const float*)d_in[3];
    const float* b2 = (const float*)d_in[4];
    float* out = (float*)d_out;

    static cudaStream_t s2 = nullptr;
    static cudaEvent_t evFork = nullptr, evW2 = nullptr;
    static bool attr_done = false;
    if (!attr_done) {
        cudaFuncSetAttribute(gemm_kernel<DIM, true, 2>,
                             cudaFuncAttributeMaxDynamicSharedMemorySize, DYN_SMEM);
        cudaFuncSetAttribute(gemm_kernel<NOUT, false, 2>,
                             cudaFuncAttributeMaxDynamicSharedMemorySize, DYN_SMEM);
        cudaStreamCreateWithFlags(&s2, cudaStreamNonBlocking);
        cudaEventCreateWithFlags(&evFork, cudaEventDisableTiming);
        cudaEventCreateWithFlags(&evW2, cudaEventDisableTiming);
        attr_done = true;
    }

    dim3 tb(32, 8);

    // fork: W2 transpose on stream 2 (only needed by GEMM2)
    cudaEventRecord(evFork, 0);
    cudaStreamWaitEvent(s2, evFork, 0);
    transpose_kernel<<<dim3(NOUT / 32, NOUT / 32), tb, 0, s2>>>(W2, NOUT, NOUT, 1);
    cudaEventRecord(evW2, s2);

    // main stream: temb chain + W1 transpose + GEMM1
    freq_kernel<<<1, 512>>>();
    temb_kernel<<<BATCH, 512>>>(t);
    transpose_kernel<<<dim3(NOUT / 32, DIM / 32), tb>>>(W1, DIM, NOUT, 0);

    dim3 grid(NOUT / BN, BATCH / (2 * BM));   // (32, 128)
    gemm_kernel<DIM, true, 2><<<grid, 128, DYN_SMEM>>>(b1, nullptr);

    // join: GEMM2 needs W2T
    cudaStreamWaitEvent(0, evW2, 0);
    gemm_kernel<NOUT, false, 2><<<grid, 128, DYN_SMEM>>>(b2, out);
}

// round 17
// speedup vs baseline: 1.2843x; 1.0055x over previous
#include <cuda_runtime.h>
#include <cuda_fp16.h>
#include <cstdint>

// ============================================================================
// TimeEmbedder: temb(t) -> standardize -> silu(x@W1+b1) -> @W2+b2
// FP16 mma.sync m16n8k16 (fp32 accum). CTA tile 128x128x64, 4 warps,
// 3-stage cp.async, 2 CTAs/SM, M-persistent x2. Launch DAG: both weight
// transposes on stream 2 under temb's shadow; fast MUFU sincos in temb.
// ============================================================================

#define DIM     1024
#define BATCH   32768
#define NOUT    4096   // DIM*EXP

// ---------------- scratch (device globals; no allocations allowed) ----------
__device__ __half g_temb[(size_t)BATCH * DIM];   // fp16 A of GEMM1 (64 MB)
__device__ __half g_w1t[(size_t)NOUT * DIM];     // [N,K] K-major fp16 (8 MB)
__device__ __half g_w2t[(size_t)NOUT * NOUT];    // [N,K] K-major fp16 (32 MB)
__device__ __half g_h[(size_t)BATCH * NOUT];     // fp16 A of GEMM2 (256 MB)
__device__ float  g_freq[DIM / 2];

// ---------------- helpers ----------------------------------------------------
__device__ __forceinline__ uint32_t smem_u32(const void* p) {
    uint32_t a;
    asm("{ .reg .u64 t; cvta.to.shared.u64 t, %1; cvt.u32.u64 %0, t; }" : "=r"(a) : "l"(p));
    return a;
}
__device__ __forceinline__ uint32_t swz128(uint32_t o) { return o ^ ((o >> 3) & 0x70u); }
__device__ __forceinline__ void cp_async16(uint32_t dst, const void* src) {
    asm volatile("cp.async.cg.shared.global [%0], [%1], 16;" :: "r"(dst), "l"(src));
}
__device__ __forceinline__ void cp_commit() { asm volatile("cp.async.commit_group;"); }

__device__ __forceinline__ void ldsm_x4(uint32_t* r, uint32_t addr) {
    asm volatile("ldmatrix.sync.aligned.m8n8.x4.shared.b16 {%0,%1,%2,%3}, [%4];"
                 : "=r"(r[0]), "=r"(r[1]), "=r"(r[2]), "=r"(r[3]) : "r"(addr));
}
__device__ __forceinline__ void mma_f16(float* c, const uint32_t* a, uint32_t b0, uint32_t b1) {
    asm volatile("mma.sync.aligned.m16n8k16.row.col.f32.f16.f16.f32 "
                 "{%0,%1,%2,%3}, {%4,%5,%6,%7}, {%8,%9}, {%0,%1,%2,%3};"
                 : "+f"(c[0]), "+f"(c[1]), "+f"(c[2]), "+f"(c[3])
                 : "r"(a[0]), "r"(a[1]), "r"(a[2]), "r"(a[3]), "r"(b0), "r"(b1));
}
// silu via hardware tanh: v * sigmoid(v) = v * (0.5 + 0.5*tanh(v/2)) — 1 MUFU
__device__ __forceinline__ float silu_fast(float v) {
    float t;
    asm("tanh.approx.f32 %0, %1;" : "=f"(t) : "f"(v * 0.5f));
    return v * fmaf(t, 0.5f, 0.5f);
}

// ============================================================================
// Kernel 0: geometric frequencies (512 threads total)
// ============================================================================
__global__ void freq_kernel() {
    int i = threadIdx.x;
    if (i < DIM / 2) {
        float ef = (float)i / 511.0f;
        g_freq[i] = (float)pow(1e-4, (double)ef);
    }
}

// ============================================================================
// Kernel 1: positional embedding + standardization -> fp16 (MUFU sincos)
// ============================================================================
__global__ void __launch_bounds__(512) temb_kernel(const float* __restrict__ t) {
    __shared__ float s_sum[16], s_ssq[16];
    __shared__ float s_mean, s_rstd;
    int b = blockIdx.x, i = threadIdx.x;

    float x = t[b] * 1000.0f;
    float p = x * g_freq[i];                      // fp32 angle, matches reference
    float c, s;
    __sincosf(p, &s, &c);                         // RRO + MUFU; abs err ~|p|*2^-24

    float sum = c + s;
    float ssq = c * c + s * s;
    #pragma unroll
    for (int o = 16; o > 0; o >>= 1) {
        sum += __shfl_xor_sync(0xFFFFFFFFu, sum, o);
        ssq += __shfl_xor_sync(0xFFFFFFFFu, ssq, o);
    }
    if ((i & 31) == 0) { s_sum[i >> 5] = sum; s_ssq[i >> 5] = ssq; }
    __syncthreads();
    if (i == 0) {
        float S = 0.f, Q = 0.f;
        #pragma unroll
        for (int w = 0; w < 16; w++) { S += s_sum[w]; Q += s_ssq[w]; }
        float mean = S / (float)DIM;
        float var  = (Q - S * S / (float)DIM) / (float)(DIM - 1);
        s_mean = mean;
        s_rstd = rsqrtf(var);
    }
    __syncthreads();
    float mean = s_mean, rstd = s_rstd;
    float cn = (c - mean) * rstd;
    float sn = (s - mean) * rstd;
    float cn1 = __shfl_down_sync(0xFFFFFFFFu, cn, 1);
    float sn1 = __shfl_down_sync(0xFFFFFFFFu, sn, 1);
    if (!(i & 1)) {
        size_t base = (size_t)b * DIM;
        *(__half2*)&g_temb[base + i] =
            __halves2half2(__float2half_rn(cn), __float2half_rn(cn1));
        *(__half2*)&g_temb[base + 512 + i] =
            __halves2half2(__float2half_rn(sn), __float2half_rn(sn1));
    }
}

// ============================================================================
// Kernel 2: W [K,N] row-major fp32 -> WT [N,K] K-major fp16 (which: 0=W1,1=W2)
// ============================================================================
__global__ void transpose_kernel(const float* __restrict__ src, int K, int N, int which) {
    __half* dst = which ? g_w2t : g_w1t;
    __shared__ float tile[32][33];
    int n0 = blockIdx.x * 32, k0 = blockIdx.y * 32;
    int tx = threadIdx.x, ty = threadIdx.y;
    #pragma unroll
    for (int i = 0; i < 32; i += 8)
        tile[ty + i][tx] = src[(size_t)(k0 + ty + i) * N + (n0 + tx)];
    __syncthreads();
    #pragma unroll
    for (int i = 0; i < 32; i += 8)
        dst[(size_t)(n0 + ty + i) * K + (k0 + tx)] = __float2half_rn(tile[tx][ty + i]);
}

// ============================================================================
// Kernel 3: FP16 mma.sync GEMM, M-persistent x MTILES.
// ============================================================================
#define BM 128
#define BN 128
#define BK 64
#define STAGES 3
#define ASTAGE (BM * BK * 2)            // 16 KB
#define BSTAGE (BN * BK * 2)            // 16 KB
#define STAGE_BYTES (ASTAGE + BSTAGE)   // 32 KB
#define DYN_SMEM (STAGES * STAGE_BYTES) // 96 KB

template <bool PHASE1>
__device__ __forceinline__ void gemm_epilogue(
    float (&c)[4][8][4], const float* s_bias, float* __restrict__ Cout,
    int m0, int n0, int warp_m, int warp_n, int lane)
{
    const int ncol0 = warp_n + (lane & 3) * 2;
    #pragma unroll
    for (int mt = 0; mt < 4; mt++) {
        int r0 = m0 + warp_m + mt * 16 + (lane >> 2);
        #pragma unroll
        for (int nt = 0; nt < 8; nt++) {
            float bv0 = s_bias[ncol0 + nt * 8];
            float bv1 = s_bias[ncol0 + nt * 8 + 1];
            float v0 = c[mt][nt][0] + bv0;
            float v1 = c[mt][nt][1] + bv1;
            float v2 = c[mt][nt][2] + bv0;
            float v3 = c[mt][nt][3] + bv1;
            if (PHASE1) {
                v0 = silu_fast(v0);
                v1 = silu_fast(v1);
                v2 = silu_fast(v2);
                v3 = silu_fast(v3);
                __half* row0 = g_h + (size_t)r0 * NOUT + (n0 + ncol0);
                __half* row1 = row0 + (size_t)8 * NOUT;
                *(__half2*)(row0 + nt * 8) =
                    __halves2half2(__float2half_rn(v0), __float2half_rn(v1));
                *(__half2*)(row1 + nt * 8) =
                    __halves2half2(__float2half_rn(v2), __float2half_rn(v3));
            } else {
                float* row0 = Cout + (size_t)r0 * NOUT + (n0 + ncol0);
                float* row1 = row0 + (size_t)8 * NOUT;
                __stcs((float2*)(row0 + nt * 8), make_float2(v0, v1));
                __stcs((float2*)(row1 + nt * 8), make_float2(v2, v3));
            }
        }
    }
}

template <int KTOT, bool PHASE1, int MTILES>
__global__ void __launch_bounds__(128, 2)
gemm_kernel(const float* __restrict__ bias, float* __restrict__ Cout) {
    const __half* A  = PHASE1 ? g_temb : g_h;
    const __half* Bt = PHASE1 ? g_w1t  : g_w2t;

    extern __shared__ char dynsmem[];
    __shared__ float s_bias[BN];

    const int tid  = threadIdx.x;
    const int wid  = tid >> 5;
    const int lane = tid & 31;
    const int n0 = blockIdx.x * BN;
    const int m0 = blockIdx.y * (MTILES * BM);   // first of MTILES m-tiles
    const int warp_m = (wid & 1) * 64;   // 0 / 64
    const int warp_n = (wid >> 1) * 64;  // 0 / 64

    const uint32_t dyn = smem_u32(dynsmem);

    if (tid < BN) s_bias[tid] = bias[n0 + tid];

    // ---- per-thread gmem->smem load plan (16B chunks = 8 halves) ----
    const char* Ab = (const char*)A;
    const char* Bb = (const char*)Bt;
    uint32_t offA[8], dA[8], offB[8], dB[8];
    #pragma unroll
    for (int j = 0; j < 8; j++) {
        uint32_t cid = (uint32_t)j * 128u + (uint32_t)tid;
        uint32_t row = cid >> 3, kc = cid & 7;
        offA[j] = (uint32_t)(m0 + row) * (uint32_t)KTOT * 2u + kc * 16u;
        dA[j]   = swz128(row * 128u + kc * 16u);
        offB[j] = (uint32_t)(n0 + row) * (uint32_t)KTOT * 2u + kc * 16u;
        dB[j]   = (uint32_t)ASTAGE + swz128(row * 128u + kc * 16u);
    }

    // ---- ldmatrix address precompute ----
    const uint32_t lane16 = lane & 15;
    const uint32_t hiA = (lane >> 4) & 1;
    uint32_t aRow[4], aXor[4];
    #pragma unroll
    for (int mt = 0; mt < 4; mt++) {
        uint32_t r = (uint32_t)(warp_m + mt * 16) + lane16;
        aRow[mt] = r * 128u;
        aXor[mt] = r & 7u;
    }
    const uint32_t nrl = (lane & 7) | ((lane >> 1) & 8);
    const uint32_t hiB = (lane >> 3) & 1;
    uint32_t bRow[4], bXor[4];
    #pragma unroll
    for (int p = 0; p < 4; p++) {
        uint32_t r = (uint32_t)(warp_n + p * 16) + nrl;
        bRow[p] = r * 128u;
        bXor[p] = r & 7u;
    }

    float c[4][8][4];
    #pragma unroll
    for (int mt = 0; mt < 4; mt++)
        #pragma unroll
        for (int nt = 0; nt < 8; nt++)
            #pragma unroll
            for (int i = 0; i < 4; i++) c[mt][nt][i] = 0.0f;

    const int nk = KTOT / BK;

    // ---- prologue: issue stages 0..STAGES-2 ----
    #pragma unroll
    for (int j = 0; j < STAGES - 1; j++) {
        uint32_t sb = dyn + (uint32_t)j * STAGE_BYTES;
        #pragma unroll
        for (int i = 0; i < 8; i++) cp_async16(sb + dA[i], Ab + offA[i]);
        #pragma unroll
        for (int i = 0; i < 8; i++) cp_async16(sb + dB[i], Bb + offB[i]);
        #pragma unroll
        for (int i = 0; i < 8; i++) { offA[i] += 128u; offB[i] += 128u; }
        cp_commit();
    }

    // fragment double buffers
    uint32_t a[2][4][4], b[2][4][4];

    for (int tt = 0; tt < MTILES; tt++) {
        #pragma unroll 4
        for (int kt = 0; kt < nk; kt++) {
            asm volatile("cp.async.wait_group %0;" :: "n"(STAGES - 2));
            __syncthreads();

            const int gi = tt * nk + kt;                 // global stage index
            const int li = gi + STAGES - 1;              // stage being loaded
            if (li < MTILES * nk) {
                if ((li % nk) == 0 && li > 0) {
                    // boundary: A jumps to next m-tile, B rewinds to k=0
                    #pragma unroll
                    for (int i = 0; i < 8; i++) {
                        offA[i] += (uint32_t)(BM - 1) * (uint32_t)KTOT * 2u;
                        offB[i] -= (uint32_t)KTOT * 2u;
                    }
                }
                uint32_t sb = dyn + (uint32_t)(li % STAGES) * STAGE_BYTES;
                #pragma unroll
                for (int i = 0; i < 8; i++) cp_async16(sb + dA[i], Ab + offA[i]);
                #pragma unroll
                for (int i = 0; i < 8; i++) cp_async16(sb + dB[i], Bb + offB[i]);
                #pragma unroll
                for (int i = 0; i < 8; i++) { offA[i] += 128u; offB[i] += 128u; }
            }
            cp_commit();

            uint32_t sA = dyn + (uint32_t)(gi % STAGES) * STAGE_BYTES;
            uint32_t sB = sA + ASTAGE;

            // ---- preload k-step 0 fragments ----
            #pragma unroll
            for (int mt = 0; mt < 4; mt++) {
                uint32_t col16 = hiA ^ aXor[mt];
                ldsm_x4(a[0][mt], sA + aRow[mt] + (col16 << 4));
            }
            #pragma unroll
            for (int p = 0; p < 4; p++) {
                uint32_t col16 = hiB ^ bXor[p];
                ldsm_x4(b[0][p], sB + bRow[p] + (col16 << 4));
            }

            // ---- pipelined k-steps: prefetch ks+1 while computing ks ----
            #pragma unroll
            for (int ks = 0; ks < 4; ks++) {
                const int cur = ks & 1, nxt = cur ^ 1;
                if (ks < 3) {
                    #pragma unroll
                    for (int mt = 0; mt < 4; mt++) {
                        uint32_t col16 = ((uint32_t)((ks + 1) * 2) + hiA) ^ aXor[mt];
                        ldsm_x4(a[nxt][mt], sA + aRow[mt] + (col16 << 4));
                    }
                    #pragma unroll
                    for (int p = 0; p < 4; p++) {
                        uint32_t col16 = ((uint32_t)((ks + 1) * 2) + hiB) ^ bXor[p];
                        ldsm_x4(b[nxt][p], sB + bRow[p] + (col16 << 4));
                    }
                }
                #pragma unroll
                for (int mt = 0; mt < 4; mt++) {
                    #pragma unroll
                    for (int nt = 0; nt < 8; nt++) {
                        const int p = nt >> 1;
                        if (nt & 1) mma_f16(c[mt][nt], a[cur][mt], b[cur][p][2], b[cur][p][3]);
                        else        mma_f16(c[mt][nt], a[cur][mt], b[cur][p][0], b[cur][p][1]);
                    }
                }
            }
        }

        // ---- epilogue for this m-tile (pipeline for next tile stays in flight) ----
        gemm_epilogue<PHASE1>(c, s_bias, Cout, m0 + tt * BM, n0, warp_m, warp_n, lane);
        if (tt + 1 < MTILES) {
            #pragma unroll
            for (int mt = 0; mt < 4; mt++)
                #pragma unroll
                for (int nt = 0; nt < 8; nt++)
                    #pragma unroll
                    for (int i = 0; i < 4; i++) c[mt][nt][i] = 0.0f;
        }
    }
}

// ============================================================================
// host launcher — both weight transposes on stream 2, overlapped with temb.
// ============================================================================
extern "C" void kernel_launch(void* const* d_in, const int* in_sizes, int n_in,
                              void* d_out, int out_size) {
    const float* t  = (const float*)d_in[0];
    const float* W1 = (const float*)d_in[1];
    const float* b1 = (const float*)d_in[2];
    const float* W2 = (const float*)d_in[3];
    const float* b2 = (const float*)d_in[4];
    float* out = (float*)d_out;

    static cudaStream_t s2 = nullptr;
    static cudaEvent_t evFork = nullptr, evW1 = nullptr, evW2 = nullptr;
    static bool attr_done = false;
    if (!attr_done) {
        cudaFuncSetAttribute(gemm_kernel<DIM, true, 2>,
                             cudaFuncAttributeMaxDynamicSharedMemorySize, DYN_SMEM);
        cudaFuncSetAttribute(gemm_kernel<NOUT, false, 2>,
                             cudaFuncAttributeMaxDynamicSharedMemorySize, DYN_SMEM);
        cudaStreamCreateWithFlags(&s2, cudaStreamNonBlocking);
        cudaEventCreateWithFlags(&evFork, cudaEventDisableTiming);
        cudaEventCreateWithFlags(&evW1, cudaEventDisableTiming);
        cudaEventCreateWithFlags(&evW2, cudaEventDisableTiming);
        attr_done = true;
    }

    dim3 tb(32, 8);

    // fork: weight transposes on stream 2 (W1T needed by GEMM1, W2T by GEMM2)
    cudaEventRecord(evFork, 0);
    cudaStreamWaitEvent(s2, evFork, 0);
    transpose_kernel<<<dim3(NOUT / 32, DIM / 32), tb, 0, s2>>>(W1, DIM, NOUT, 0);
    cudaEventRecord(evW1, s2);
    transpose_kernel<<<dim3(NOUT / 32, NOUT / 32), tb, 0, s2>>>(W2, NOUT, NOUT, 1);
    cudaEventRecord(evW2, s2);

    // main stream: temb chain
    freq_kernel<<<1, 512>>>();
    temb_kernel<<<BATCH, 512>>>(t);

    dim3 grid(NOUT / BN, BATCH / (2 * BM));   // (32, 128)
    cudaStreamWaitEvent(0, evW1, 0);
    gemm_kernel<DIM, true, 2><<<grid, 128, DYN_SMEM>>>(b1, nullptr);

    cudaStreamWaitEvent(0, evW2, 0);
    gemm_kernel<NOUT, false, 2><<<grid, 128, DYN_SMEM>>>(b2, out);
}